// round 3
// baseline (speedup 1.0000x reference)
#include <cuda_runtime.h>
#include <math.h>

// ---------------------------------------------------------------------------
// Problem constants
// ---------------------------------------------------------------------------
#define BB   8
#define HH   64
#define WW   64
#define CV   256
#define CT   512
#define TT   100
#define NN_  4096            // H*W
#define ROWS (BB*NN_)        // 32768
#define TOPM 5

// ---------------------------------------------------------------------------
// Scratch (static device globals: allocation-free)
// ---------------------------------------------------------------------------
__device__ float g_x   [ROWS * CV];       // ln1 output
__device__ float g_gate[ROWS];            // sigmoid gate
__device__ float g_q   [ROWS * CT];       // l2norm(x@qw+qb)
__device__ float g_kn  [BB * TT * CT];    // l2norm(text)
__device__ float g_v   [BB * TT * CV];    // text@vw+vb
__device__ int   g_pad [BB * TT];
__device__ float g_sim [ROWS * TT];       // unscaled q.k
__device__ float g_y   [ROWS * CV];       // after aligned residual
__device__ float g_y2  [ROWS * CV];       // ln2 output
__device__ float g_h   [ROWS * 4 * CV];   // gelu hidden

// ---------------------------------------------------------------------------
// Block reduction helper (256 threads)
// ---------------------------------------------------------------------------
__device__ __forceinline__ float block_reduce_sum(float v, float* sbuf) {
    int lane = threadIdx.x & 31, w = threadIdx.x >> 5;
    #pragma unroll
    for (int o = 16; o; o >>= 1) v += __shfl_xor_sync(0xffffffffu, v, o);
    if (lane == 0) sbuf[w] = v;
    __syncthreads();
    float r = (threadIdx.x < (blockDim.x >> 5)) ? sbuf[threadIdx.x] : 0.f;
    if (w == 0) {
        #pragma unroll
        for (int o = 16; o; o >>= 1) r += __shfl_xor_sync(0xffffffffu, r, o);
        if (lane == 0) sbuf[0] = r;
    }
    __syncthreads();
    r = sbuf[0];
    __syncthreads();   // safe to reuse sbuf after return
    return r;
}

// ---------------------------------------------------------------------------
// Kernel 1: LayerNorm1 + gate
// ---------------------------------------------------------------------------
__global__ void ln1_gate_kernel(const float* __restrict__ vis,
                                const float* __restrict__ g, const float* __restrict__ b,
                                const float* __restrict__ gw, const float* __restrict__ gb) {
    __shared__ float sbuf[32];
    long row = blockIdx.x;
    int c = threadIdx.x;
    float v = vis[row * CV + c];
    float mean = block_reduce_sum(v, sbuf) * (1.f / CV);
    float d = v - mean;
    float var = block_reduce_sum(d * d, sbuf) * (1.f / CV);
    float xv = d * rsqrtf(var + 1e-5f) * g[c] + b[c];
    g_x[row * CV + c] = xv;
    float gl = block_reduce_sum(xv * gw[c], sbuf);
    if (c == 0) g_gate[row] = 1.f / (1.f + expf(-(gl + gb[0])));
}

// ---------------------------------------------------------------------------
// Kernel: LayerNorm2 (g_y -> g_y2)
// ---------------------------------------------------------------------------
__global__ void ln2_kernel(const float* __restrict__ g, const float* __restrict__ b) {
    __shared__ float sbuf[32];
    long row = blockIdx.x;
    int c = threadIdx.x;
    float v = g_y[row * CV + c];
    float mean = block_reduce_sum(v, sbuf) * (1.f / CV);
    float d = v - mean;
    float var = block_reduce_sum(d * d, sbuf) * (1.f / CV);
    g_y2[row * CV + c] = d * rsqrtf(var + 1e-5f) * g[c] + b[c];
}

// ---------------------------------------------------------------------------
// Kernel: l2-normalize rows of 512 (in place, on g_q)
// ---------------------------------------------------------------------------
__global__ void l2norm_rows512(float* __restrict__ q) {
    __shared__ float sbuf[32];
    long base = (long)blockIdx.x * CT;
    float a = q[base + threadIdx.x];
    float c = q[base + threadIdx.x + 256];
    float ss = block_reduce_sum(a * a + c * c, sbuf);
    float inv = 1.f / fmaxf(sqrtf(ss), 1e-6f);
    q[base + threadIdx.x]       = a * inv;
    q[base + threadIdx.x + 256] = c * inv;
}

// ---------------------------------------------------------------------------
// Kernel: text prep — k = l2norm(text), pad flag
// ---------------------------------------------------------------------------
__global__ void text_prep_kernel(const float* __restrict__ text) {
    __shared__ float sbuf[32];
    long base = (long)blockIdx.x * CT;
    float a = text[base + threadIdx.x];
    float c = text[base + threadIdx.x + 256];
    float sa = block_reduce_sum(fabsf(a) + fabsf(c), sbuf);
    float ss = block_reduce_sum(a * a + c * c, sbuf);
    if (threadIdx.x == 0) g_pad[blockIdx.x] = (sa <= 1e-6f) ? 1 : 0;
    float inv = 1.f / fmaxf(sqrtf(ss), 1e-6f);
    g_kn[base + threadIdx.x]       = a * inv;
    g_kn[base + threadIdx.x + 256] = c * inv;
}

// ---------------------------------------------------------------------------
// Generic tiled SGEMM: C[M,N] = A[M,K] * B (+bias, epilogue)
//   TB=false: B is [K,N] row-major.  TB=true: B is [N,K] row-major (B^T).
//   EPI 0: none   1: exact GELU   2: + residual R[M,N]
//   blockIdx.z batching via element strides sA,sB,sC (R shares sC).
// 128x128 tile, BK=16, 256 threads, 8x8 per thread.
// ---------------------------------------------------------------------------
template<bool TB, int EPI>
__global__ __launch_bounds__(256) void sgemm_kernel(
    const float* __restrict__ A, const float* __restrict__ B,
    const float* __restrict__ bias, const float* __restrict__ R,
    float* __restrict__ C, int M, int N, int K,
    long sA, long sB, long sC)
{
    __shared__ float As[16][132];
    __shared__ float Bs[16][128];
    A += (long)blockIdx.z * sA;
    B += (long)blockIdx.z * sB;
    C += (long)blockIdx.z * sC;
    if (EPI == 2) R += (long)blockIdx.z * sC;

    int tid = threadIdx.x;
    int m0 = blockIdx.y * 128, n0 = blockIdx.x * 128;
    int tx = tid & 15, ty = tid >> 4;

    float acc[8][8];
    #pragma unroll
    for (int i = 0; i < 8; i++)
        #pragma unroll
        for (int j = 0; j < 8; j++) acc[i][j] = 0.f;

    for (int k0 = 0; k0 < K; k0 += 16) {
        // ---- load A tile (transposed into As[k][m]) ----
        #pragma unroll
        for (int i = 0; i < 2; i++) {
            int p = tid + 256 * i;
            int r = p >> 2, cc = (p & 3) * 4;
            float4 av = make_float4(0.f, 0.f, 0.f, 0.f);
            if (m0 + r < M) av = *(const float4*)(A + (long)(m0 + r) * K + k0 + cc);
            As[cc + 0][r] = av.x; As[cc + 1][r] = av.y;
            As[cc + 2][r] = av.z; As[cc + 3][r] = av.w;
        }
        // ---- load B tile into Bs[k][n] ----
        if (!TB) {
            #pragma unroll
            for (int i = 0; i < 2; i++) {
                int p = tid + 256 * i;
                int r = p >> 5, cc = (p & 31) * 4;
                float4 bv = *(const float4*)(B + (long)(k0 + r) * N + n0 + cc);
                *(float4*)&Bs[r][cc] = bv;
            }
        } else {
            #pragma unroll
            for (int i = 0; i < 2; i++) {
                int p = tid + 256 * i;
                int r = p >> 2, cc = (p & 3) * 4;   // r: n-offset, cc: k-offset
                float4 bv = make_float4(0.f, 0.f, 0.f, 0.f);
                if (n0 + r < N) bv = *(const float4*)(B + (long)(n0 + r) * K + k0 + cc);
                Bs[cc + 0][r] = bv.x; Bs[cc + 1][r] = bv.y;
                Bs[cc + 2][r] = bv.z; Bs[cc + 3][r] = bv.w;
            }
        }
        __syncthreads();

        #pragma unroll
        for (int kk = 0; kk < 16; kk++) {
            float a[8], bb[8];
            *(float4*)&a[0]  = *(const float4*)&As[kk][ty * 8];
            *(float4*)&a[4]  = *(const float4*)&As[kk][ty * 8 + 4];
            *(float4*)&bb[0] = *(const float4*)&Bs[kk][tx * 8];
            *(float4*)&bb[4] = *(const float4*)&Bs[kk][tx * 8 + 4];
            #pragma unroll
            for (int i = 0; i < 8; i++)
                #pragma unroll
                for (int j = 0; j < 8; j++)
                    acc[i][j] = fmaf(a[i], bb[j], acc[i][j]);
        }
        __syncthreads();
    }

    #pragma unroll
    for (int i = 0; i < 8; i++) {
        int m = m0 + ty * 8 + i;
        if (m >= M) continue;
        #pragma unroll
        for (int j = 0; j < 8; j++) {
            int n = n0 + tx * 8 + j;
            if (n >= N) continue;
            float r = acc[i][j];
            if (bias) r += bias[n];
            if (EPI == 1) r = 0.5f * r * (1.f + erff(r * 0.70710678118654752f));
            if (EPI == 2) r += R[(long)m * N + n];
            C[(long)m * N + n] = r;
        }
    }
}

// ---------------------------------------------------------------------------
// Kernel: per-row top-5 over 100 sims + pad mask + softmax + gather + combine
// One warp per (b,n) row. 8 warps per block.
// ---------------------------------------------------------------------------
__global__ void topk_combine_kernel(const float* __restrict__ logit_scale,
                                    const float* __restrict__ alpha_p) {
    int warp = (blockIdx.x * blockDim.x + threadIdx.x) >> 5;
    int lane = threadIdx.x & 31;
    if (warp >= ROWS) return;
    int b = warp >> 12;                  // 4096 rows per batch

    float ls = logit_scale[0];
    float scale = expf(fminf(fmaxf(ls, -2.f), 2.f)) * rsqrtf((float)CT);
    float alpha = alpha_p[0];

    const float* srow = g_sim + (long)warp * TT;
    float vals[4]; int idxs[4];
    #pragma unroll
    for (int i = 0; i < 4; i++) {
        int t = lane + 32 * i;
        if (t < TT) { vals[i] = srow[t] * scale; idxs[i] = t; }
        else        { vals[i] = -INFINITY;       idxs[i] = 0x7fffffff; }
    }

    float wv[TOPM]; int wi[TOPM];
    #pragma unroll
    for (int m = 0; m < TOPM; m++) {
        float bv = vals[0]; int bi = idxs[0];
        #pragma unroll
        for (int i = 1; i < 4; i++)
            if (vals[i] > bv || (vals[i] == bv && idxs[i] < bi)) { bv = vals[i]; bi = idxs[i]; }
        float rv = bv; int ri = bi;
        #pragma unroll
        for (int off = 16; off; off >>= 1) {
            float ov = __shfl_xor_sync(0xffffffffu, rv, off);
            int   oi = __shfl_xor_sync(0xffffffffu, ri, off);
            if (ov > rv || (ov == rv && oi < ri)) { rv = ov; ri = oi; }
        }
        wv[m] = rv; wi[m] = ri;
        if ((ri & 31) == lane) {        // owning lane removes it
            int s = ri >> 5;
            vals[s] = -INFINITY; idxs[s] = 0x7fffffff;
        }
    }

    // pad mask + softmax over 5
    float mx = -INFINITY;
    #pragma unroll
    for (int m = 0; m < TOPM; m++) {
        if (g_pad[b * TT + wi[m]]) wv[m] = -INFINITY;
        mx = fmaxf(mx, wv[m]);
    }
    float e[TOPM]; float se = 0.f;
    #pragma unroll
    for (int m = 0; m < TOPM; m++) {
        e[m] = (wv[m] == -INFINITY) ? 0.f : expf(wv[m] - mx);
        se += e[m];
    }
    float inv = 1.f / se;
    float ag = alpha * g_gate[warp];

    long rowoff = (long)warp * CV;
    #pragma unroll
    for (int j = 0; j < CV / 32; j++) {
        int c = lane + 32 * j;
        float acc = 0.f;
        #pragma unroll
        for (int m = 0; m < TOPM; m++)
            acc = fmaf(e[m] * inv, g_v[(long)(b * TT + wi[m]) * CV + c], acc);
        g_y[rowoff + c] = g_x[rowoff + c] + ag * acc;
    }
}

// ---------------------------------------------------------------------------
// Launch
// ---------------------------------------------------------------------------
static float* symaddr(const void* sym) {
    void* p = nullptr;
    cudaGetSymbolAddress(&p, sym);
    return (float*)p;
}

extern "C" void kernel_launch(void* const* d_in, const int* in_sizes, int n_in,
                              void* d_out, int out_size) {
    const float* visual = (const float*)d_in[0];
    const float* text   = (const float*)d_in[1];
    const float* ln1_g  = (const float*)d_in[2];
    const float* ln1_b  = (const float*)d_in[3];
    const float* qw     = (const float*)d_in[4];
    const float* qb     = (const float*)d_in[5];
    const float* vw     = (const float*)d_in[6];
    const float* vb     = (const float*)d_in[7];
    const float* gate_w = (const float*)d_in[8];
    const float* gate_b = (const float*)d_in[9];
    const float* lscale = (const float*)d_in[10];
    const float* alpha  = (const float*)d_in[11];
    const float* ln2_g  = (const float*)d_in[12];
    const float* ln2_b  = (const float*)d_in[13];
    const float* w1     = (const float*)d_in[14];
    const float* b1     = (const float*)d_in[15];
    const float* w2     = (const float*)d_in[16];
    const float* b2     = (const float*)d_in[17];
    float* out = (float*)d_out;

    float* px  = symaddr(g_x);
    float* pq  = symaddr(g_q);
    float* pkn = symaddr(g_kn);
    float* pv  = symaddr(g_v);
    float* ps  = symaddr(g_sim);
    float* py2 = symaddr(g_y2);
    float* ph  = symaddr(g_h);

    // 1. LN1 + gate
    ln1_gate_kernel<<<ROWS, 256>>>(visual, ln1_g, ln1_b, gate_w, gate_b);

    // 2. Q = x @ qw + qb   (32768 x 512 x 256)
    sgemm_kernel<false, 0><<<dim3(CT / 128, ROWS / 128, 1), 256>>>(
        px, qw, qb, nullptr, pq, ROWS, CT, CV, 0, 0, 0);

    // 3. l2norm(q)
    l2norm_rows512<<<ROWS, 256>>>(pq);

    // 4. k-norm + pad flags
    text_prep_kernel<<<BB * TT, 256>>>(text);

    // 5. V = text @ vw + vb   (800 x 256 x 512)
    sgemm_kernel<false, 0><<<dim3(CV / 128, (BB * TT + 127) / 128, 1), 256>>>(
        text, vw, vb, nullptr, pv, BB * TT, CV, CT, 0, 0, 0);

    // 6. sim = q @ k^T  per batch  (4096 x 100 x 512, batched over z)
    sgemm_kernel<true, 0><<<dim3(1, NN_ / 128, BB), 256>>>(
        pq, pkn, nullptr, nullptr, ps, NN_, TT, CT,
        (long)NN_ * CT, (long)TT * CT, (long)NN_ * TT);

    // 7. top-5 + softmax + gather + gate + residual -> g_y
    topk_combine_kernel<<<ROWS / 8, 256>>>(lscale, alpha);

    // 8. LN2
    ln2_kernel<<<ROWS, 256>>>(ln2_g, ln2_b);

    // 9. h = gelu(y2 @ w1 + b1)   (32768 x 1024 x 256)
    sgemm_kernel<false, 1><<<dim3(4 * CV / 128, ROWS / 128, 1), 256>>>(
        py2, w1, b1, nullptr, ph, ROWS, 4 * CV, CV, 0, 0, 0);

    // 10. out = y2 + h @ w2 + b2   (32768 x 256 x 1024)
    sgemm_kernel<false, 2><<<dim3(CV / 128, ROWS / 128, 1), 256>>>(
        ph, w2, b2, py2, out, ROWS, CV, 4 * CV, 0, 0, 0);
}

// round 5
// speedup vs baseline: 2.2792x; 2.2792x over previous
#include <cuda_runtime.h>
#include <math.h>
#include <cstdint>

// ---------------------------------------------------------------------------
// Problem constants
// ---------------------------------------------------------------------------
#define BB   8
#define CV   256
#define CT   512
#define TT   100
#define TPAD 128            // padded text rows for sim GEMM
#define NN_  4096           // H*W
#define ROWS (BB*NN_)       // 32768
#define TOPM 5

// ---------------------------------------------------------------------------
// Scratch (static device globals: allocation-free)
// ---------------------------------------------------------------------------
__device__ float g_x   [ROWS * CV];        // ln1 output
__device__ float g_gate[ROWS];             // sigmoid gate
__device__ float g_q   [ROWS * CT];        // l2norm(x@qw+qb)
__device__ float g_kn  [BB * TPAD * CT];   // l2norm(text), padded to 128 rows
__device__ float g_v   [BB * TT * CV];     // text@vw+vb
__device__ int   g_pad [BB * TT];
__device__ float g_sim [ROWS * TT];        // unscaled q.k
__device__ float g_y   [ROWS * CV];        // after aligned residual
__device__ float g_y2  [ROWS * CV];        // ln2 output
__device__ float g_h   [ROWS * 4 * CV];    // gelu hidden
// transposed weights ([N,K] K-major = B^T for the NT GEMM)
__device__ float g_qwt [CT * CV];          // [512,256]
__device__ float g_vwt [CV * CT];          // [256,512]
__device__ float g_w1t [4*CV * CV];        // [1024,256]
__device__ float g_w2t [CV * 4*CV];        // [256,1024]

// ---------------------------------------------------------------------------
// PTX helpers
// ---------------------------------------------------------------------------
__device__ __forceinline__ uint32_t smem_to_u32(const void* p) {
    uint32_t a;
    asm("{ .reg .u64 t; cvta.to.shared.u64 t, %1; cvt.u32.u64 %0, t; }"
        : "=r"(a) : "l"(p));
    return a;
}
__device__ __forceinline__ void cp16(uint32_t dst, const float* src, bool pred) {
    int sz = pred ? 16 : 0;
    asm volatile("cp.async.cg.shared.global [%0], [%1], 16, %2;\n"
        :: "r"(dst), "l"(src), "r"(sz));
}
__device__ __forceinline__ uint32_t f2tf(float x) {
    uint32_t u;
    asm("cvt.rna.tf32.f32 %0, %1;" : "=r"(u) : "f"(x));
    return u;
}
__device__ __forceinline__ void mma8(float* c, const uint32_t* a, const uint32_t* b) {
    asm volatile(
        "mma.sync.aligned.m16n8k8.row.col.f32.tf32.tf32.f32 "
        "{%0,%1,%2,%3},{%4,%5,%6,%7},{%8,%9},{%0,%1,%2,%3};"
        : "+f"(c[0]), "+f"(c[1]), "+f"(c[2]), "+f"(c[3])
        : "r"(a[0]), "r"(a[1]), "r"(a[2]), "r"(a[3]), "r"(b[0]), "r"(b[1]));
}

// ---------------------------------------------------------------------------
// Block reduction helper (256 threads)
// ---------------------------------------------------------------------------
__device__ __forceinline__ float block_reduce_sum(float v, float* sbuf) {
    int lane = threadIdx.x & 31, w = threadIdx.x >> 5;
    #pragma unroll
    for (int o = 16; o; o >>= 1) v += __shfl_xor_sync(0xffffffffu, v, o);
    if (lane == 0) sbuf[w] = v;
    __syncthreads();
    float r = (threadIdx.x < (blockDim.x >> 5)) ? sbuf[threadIdx.x] : 0.f;
    if (w == 0) {
        #pragma unroll
        for (int o = 16; o; o >>= 1) r += __shfl_xor_sync(0xffffffffu, r, o);
        if (lane == 0) sbuf[0] = r;
    }
    __syncthreads();
    r = sbuf[0];
    __syncthreads();
    return r;
}

// ---------------------------------------------------------------------------
// Elementwise kernels
// ---------------------------------------------------------------------------
__global__ void ln1_gate_kernel(const float* __restrict__ vis,
                                const float* __restrict__ g, const float* __restrict__ b,
                                const float* __restrict__ gw, const float* __restrict__ gb) {
    __shared__ float sbuf[32];
    long row = blockIdx.x;
    int c = threadIdx.x;
    float v = vis[row * CV + c];
    float mean = block_reduce_sum(v, sbuf) * (1.f / CV);
    float d = v - mean;
    float var = block_reduce_sum(d * d, sbuf) * (1.f / CV);
    float xv = d * rsqrtf(var + 1e-5f) * g[c] + b[c];
    g_x[row * CV + c] = xv;
    float gl = block_reduce_sum(xv * gw[c], sbuf);
    if (c == 0) g_gate[row] = 1.f / (1.f + expf(-(gl + gb[0])));
}

__global__ void ln2_kernel(const float* __restrict__ g, const float* __restrict__ b) {
    __shared__ float sbuf[32];
    long row = blockIdx.x;
    int c = threadIdx.x;
    float v = g_y[row * CV + c];
    float mean = block_reduce_sum(v, sbuf) * (1.f / CV);
    float d = v - mean;
    float var = block_reduce_sum(d * d, sbuf) * (1.f / CV);
    g_y2[row * CV + c] = d * rsqrtf(var + 1e-5f) * g[c] + b[c];
}

__global__ void l2norm_rows512(float* __restrict__ q) {
    __shared__ float sbuf[32];
    long base = (long)blockIdx.x * CT;
    float a = q[base + threadIdx.x];
    float c = q[base + threadIdx.x + 256];
    float ss = block_reduce_sum(a * a + c * c, sbuf);
    float inv = 1.f / fmaxf(sqrtf(ss), 1e-6f);
    q[base + threadIdx.x]       = a * inv;
    q[base + threadIdx.x + 256] = c * inv;
}

// k = l2norm(text) into padded [BB][TPAD][CT]; pad flags; zero rows >= TT
__global__ void text_prep_kernel(const float* __restrict__ text) {
    __shared__ float sbuf[32];
    int blk = blockIdx.x;                // b*TPAD + t
    int b = blk >> 7, t = blk & (TPAD - 1);
    long kbase = (long)blk * CT;
    if (t >= TT) {
        g_kn[kbase + threadIdx.x]       = 0.f;
        g_kn[kbase + threadIdx.x + 256] = 0.f;
        return;
    }
    long base = ((long)b * TT + t) * CT;
    float a = text[base + threadIdx.x];
    float c = text[base + threadIdx.x + 256];
    float sa = block_reduce_sum(fabsf(a) + fabsf(c), sbuf);
    float ss = block_reduce_sum(a * a + c * c, sbuf);
    if (threadIdx.x == 0) g_pad[b * TT + t] = (sa <= 1e-6f) ? 1 : 0;
    float inv = 1.f / fmaxf(sqrtf(ss), 1e-6f);
    g_kn[kbase + threadIdx.x]       = a * inv;
    g_kn[kbase + threadIdx.x + 256] = c * inv;
}

// 32x32 tiled transpose: dst[n*K+k] = src[k*N+n]
__global__ void transpose_kernel(const float* __restrict__ src, float* __restrict__ dst,
                                 int Kd, int Nd) {
    __shared__ float t[32][33];
    int k0 = blockIdx.y * 32, n0 = blockIdx.x * 32;
    int x = threadIdx.x, y = threadIdx.y;
    #pragma unroll
    for (int i = 0; i < 32; i += 8)
        t[y + i][x] = src[(long)(k0 + y + i) * Nd + n0 + x];
    __syncthreads();
    #pragma unroll
    for (int i = 0; i < 32; i += 8)
        dst[(long)(n0 + y + i) * Kd + k0 + x] = t[x][y + i];
}

// ---------------------------------------------------------------------------
// tf32 mma.sync GEMM: C[M,N] = A[M,K] · Bt[N,K]^T (+bias/epilogue)
//   EPI 0: none   1: exact GELU   2: + residual R
// CTA tile 128x128, BK=32, 256 threads (8 warps, 2x4), warp tile 64x32.
// SMEM: [128 rows][36 floats] padded (conflict-free fragment LDS).
// cp.async 2-stage double buffer.
// ---------------------------------------------------------------------------
#define SPITCH 36                       // floats per smem row
#define TILE_F (128 * SPITCH)           // 4608 floats per tile
#define STAGE_F (2 * TILE_F)            // A+B per stage
#define SMEM_BYTES (2 * STAGE_F * 4)    // 73728 bytes

template<int EPI>
__global__ __launch_bounds__(256, 2) void mma_gemm(
    const float* __restrict__ A, const float* __restrict__ Bt,
    const float* __restrict__ bias, const float* __restrict__ R,
    float* __restrict__ C, int M, int N, int K,
    int ldc, int n_store, long sA, long sB, long sC)
{
    extern __shared__ float smem[];
    uint32_t sbase = smem_to_u32(smem);

    A  += (long)blockIdx.z * sA;
    Bt += (long)blockIdx.z * sB;
    C  += (long)blockIdx.z * sC;
    const float* Rp = (EPI == 2) ? (R + (long)blockIdx.z * sC) : nullptr;

    int tid = threadIdx.x, wid = tid >> 5, lane = tid & 31;
    int wm = wid & 1, wn = wid >> 1;          // warp grid 2 (M) x 4 (N)
    int lr = lane >> 2, lc = lane & 3;
    int m0 = blockIdx.y * 128, n0 = blockIdx.x * 128;

    float acc[4][4][4];
    #pragma unroll
    for (int i = 0; i < 4; i++)
        #pragma unroll
        for (int j = 0; j < 4; j++)
            #pragma unroll
            for (int e = 0; e < 4; e++) acc[i][j][e] = 0.f;

    int nc = K >> 5;

    // load chunk kc into stage buf
    auto load_chunk = [&](int buf, int kc) {
        uint32_t a_s = sbase + (uint32_t)(buf * STAGE_F) * 4u;
        uint32_t b_s = a_s + (uint32_t)TILE_F * 4u;
        long koff = (long)kc * 32;
        #pragma unroll
        for (int i = 0; i < 4; i++) {
            int p = tid + 256 * i;                 // 0..1023
            int r = p >> 3, k4 = (p & 7) * 4;
            uint32_t off = (uint32_t)(r * SPITCH + k4) * 4u;
            cp16(a_s + off, A + (long)(m0 + r) * K + koff + k4, (m0 + r) < M);
        }
        #pragma unroll
        for (int i = 0; i < 4; i++) {
            int p = tid + 256 * i;
            int r = p >> 3, k4 = (p & 7) * 4;
            uint32_t off = (uint32_t)(r * SPITCH + k4) * 4u;
            cp16(b_s + off, Bt + (long)(n0 + r) * K + koff + k4, (n0 + r) < N);
        }
        asm volatile("cp.async.commit_group;\n" ::: "memory");
    };

    load_chunk(0, 0);
    if (nc > 1) load_chunk(1, 1);

    for (int c = 0; c < nc; c++) {
        int buf = c & 1;
        if (c == nc - 1) asm volatile("cp.async.wait_group 0;\n" ::: "memory");
        else             asm volatile("cp.async.wait_group 1;\n" ::: "memory");
        __syncthreads();

        const float* Ab = smem + buf * STAGE_F;
        const float* Bb = Ab + TILE_F;
        const float* Abase = Ab + (wm * 64 + lr) * SPITCH + lc;
        const float* Bbase = Bb + (wn * 32 + lr) * SPITCH + lc;

        #pragma unroll
        for (int ks = 0; ks < 4; ks++) {
            int kb = ks * 8;
            uint32_t af[4][4], bf[4][2];
            #pragma unroll
            for (int mi = 0; mi < 4; mi++) {
                const float* p = Abase + mi * 16 * SPITCH + kb;
                af[mi][0] = f2tf(p[0]);
                af[mi][1] = f2tf(p[8 * SPITCH]);
                af[mi][2] = f2tf(p[4]);
                af[mi][3] = f2tf(p[8 * SPITCH + 4]);
            }
            #pragma unroll
            for (int ni = 0; ni < 4; ni++) {
                const float* p = Bbase + ni * 8 * SPITCH + kb;
                bf[ni][0] = f2tf(p[0]);
                bf[ni][1] = f2tf(p[4]);
            }
            #pragma unroll
            for (int mi = 0; mi < 4; mi++)
                #pragma unroll
                for (int ni = 0; ni < 4; ni++)
                    mma8(acc[mi][ni], af[mi], bf[ni]);
        }
        __syncthreads();
        if (c + 2 < nc) load_chunk(buf, c + 2);
    }

    // ---- epilogue ----
    #pragma unroll
    for (int mi = 0; mi < 4; mi++) {
        #pragma unroll
        for (int half = 0; half < 2; half++) {
            int m = m0 + wm * 64 + mi * 16 + lr + half * 8;
            if (m >= M) continue;
            #pragma unroll
            for (int ni = 0; ni < 4; ni++) {
                int n = n0 + wn * 32 + ni * 8 + 2 * lc;
                #pragma unroll
                for (int e = 0; e < 2; e++) {
                    int ne = n + e;
                    if (ne >= n_store) continue;
                    float x = acc[mi][ni][half * 2 + e];
                    if (bias) x += bias[ne];
                    if (EPI == 1) x = 0.5f * x * (1.f + erff(x * 0.70710678118654752f));
                    if (EPI == 2) x += Rp[(long)m * ldc + ne];
                    C[(long)m * ldc + ne] = x;
                }
            }
        }
    }
}

// ---------------------------------------------------------------------------
// top-5 + softmax + gather + gate + residual (one warp per pixel)
// ---------------------------------------------------------------------------
__global__ void topk_combine_kernel(const float* __restrict__ logit_scale,
                                    const float* __restrict__ alpha_p) {
    int warp = (blockIdx.x * blockDim.x + threadIdx.x) >> 5;
    int lane = threadIdx.x & 31;
    if (warp >= ROWS) return;
    int b = warp >> 12;

    float ls = logit_scale[0];
    float scale = expf(fminf(fmaxf(ls, -2.f), 2.f)) * rsqrtf((float)CT);
    float alpha = alpha_p[0];

    const float* srow = g_sim + (long)warp * TT;
    float vals[4]; int idxs[4];
    #pragma unroll
    for (int i = 0; i < 4; i++) {
        int t = lane + 32 * i;
        if (t < TT) { vals[i] = srow[t] * scale; idxs[i] = t; }
        else        { vals[i] = -INFINITY;       idxs[i] = 0x7fffffff; }
    }

    float wv[TOPM]; int wi[TOPM];
    #pragma unroll
    for (int m = 0; m < TOPM; m++) {
        float bv = vals[0]; int bi = idxs[0];
        #pragma unroll
        for (int i = 1; i < 4; i++)
            if (vals[i] > bv || (vals[i] == bv && idxs[i] < bi)) { bv = vals[i]; bi = idxs[i]; }
        float rv = bv; int ri = bi;
        #pragma unroll
        for (int off = 16; off; off >>= 1) {
            float ov = __shfl_xor_sync(0xffffffffu, rv, off);
            int   oi = __shfl_xor_sync(0xffffffffu, ri, off);
            if (ov > rv || (ov == rv && oi < ri)) { rv = ov; ri = oi; }
        }
        wv[m] = rv; wi[m] = ri;
        if ((ri & 31) == lane) {
            int s = ri >> 5;
            vals[s] = -INFINITY; idxs[s] = 0x7fffffff;
        }
    }

    float mx = -INFINITY;
    #pragma unroll
    for (int m = 0; m < TOPM; m++) {
        if (g_pad[b * TT + wi[m]]) wv[m] = -INFINITY;
        mx = fmaxf(mx, wv[m]);
    }
    float e[TOPM]; float se = 0.f;
    #pragma unroll
    for (int m = 0; m < TOPM; m++) {
        e[m] = (wv[m] == -INFINITY) ? 0.f : expf(wv[m] - mx);
        se += e[m];
    }
    float inv = 1.f / se;
    float ag = alpha * g_gate[warp];

    long rowoff = (long)warp * CV;
    #pragma unroll
    for (int j = 0; j < CV / 32; j++) {
        int c = lane + 32 * j;
        float acc = 0.f;
        #pragma unroll
        for (int m = 0; m < TOPM; m++)
            acc = fmaf(e[m] * inv, g_v[(long)(b * TT + wi[m]) * CV + c], acc);
        g_y[rowoff + c] = g_x[rowoff + c] + ag * acc;
    }
}

// ---------------------------------------------------------------------------
// Launch
// ---------------------------------------------------------------------------
static float* symaddr(const void* sym) {
    void* p = nullptr;
    cudaGetSymbolAddress(&p, sym);
    return (float*)p;
}

extern "C" void kernel_launch(void* const* d_in, const int* in_sizes, int n_in,
                              void* d_out, int out_size) {
    const float* visual = (const float*)d_in[0];
    const float* text   = (const float*)d_in[1];
    const float* ln1_g  = (const float*)d_in[2];
    const float* ln1_b  = (const float*)d_in[3];
    const float* qw     = (const float*)d_in[4];
    const float* qb     = (const float*)d_in[5];
    const float* vw     = (const float*)d_in[6];
    const float* vb     = (const float*)d_in[7];
    const float* gate_w = (const float*)d_in[8];
    const float* gate_b = (const float*)d_in[9];
    const float* lscale = (const float*)d_in[10];
    const float* alpha  = (const float*)d_in[11];
    const float* ln2_g  = (const float*)d_in[12];
    const float* ln2_b  = (const float*)d_in[13];
    const float* w1     = (const float*)d_in[14];
    const float* b1     = (const float*)d_in[15];
    const float* w2     = (const float*)d_in[16];
    const float* b2     = (const float*)d_in[17];
    float* out = (float*)d_out;

    float* px   = symaddr(g_x);
    float* pq   = symaddr(g_q);
    float* pkn  = symaddr(g_kn);
    float* pv   = symaddr(g_v);
    float* ps   = symaddr(g_sim);
    float* py2  = symaddr(g_y2);
    float* ph   = symaddr(g_h);
    float* pqwt = symaddr(g_qwt);
    float* pvwt = symaddr(g_vwt);
    float* pw1t = symaddr(g_w1t);
    float* pw2t = symaddr(g_w2t);

    cudaFuncSetAttribute(mma_gemm<0>, cudaFuncAttributeMaxDynamicSharedMemorySize, SMEM_BYTES);
    cudaFuncSetAttribute(mma_gemm<1>, cudaFuncAttributeMaxDynamicSharedMemorySize, SMEM_BYTES);
    cudaFuncSetAttribute(mma_gemm<2>, cudaFuncAttributeMaxDynamicSharedMemorySize, SMEM_BYTES);

    // 0. weight transposes (tiny)
    transpose_kernel<<<dim3(CT/32, CV/32), dim3(32,8)>>>(qw, pqwt, CV, CT);
    transpose_kernel<<<dim3(CV/32, CT/32), dim3(32,8)>>>(vw, pvwt, CT, CV);
    transpose_kernel<<<dim3(4*CV/32, CV/32), dim3(32,8)>>>(w1, pw1t, CV, 4*CV);
    transpose_kernel<<<dim3(CV/32, 4*CV/32), dim3(32,8)>>>(w2, pw2t, 4*CV, CV);

    // 1. LN1 + gate
    ln1_gate_kernel<<<ROWS, 256>>>(visual, ln1_g, ln1_b, gate_w, gate_b);

    // 2. Q = x @ qw + qb   (32768 x 512 x 256)
    mma_gemm<0><<<dim3(CT/128, ROWS/128, 1), 256, SMEM_BYTES>>>(
        px, pqwt, qb, nullptr, pq, ROWS, CT, CV, CT, CT, 0, 0, 0);

    // 3. l2norm(q)
    l2norm_rows512<<<ROWS, 256>>>(pq);

    // 4. k-norm (padded) + pad flags
    text_prep_kernel<<<BB * TPAD, 256>>>(text);

    // 5. V = text @ vw + vb   (800 x 256 x 512)
    mma_gemm<0><<<dim3(CV/128, (BB*TT + 127)/128, 1), 256, SMEM_BYTES>>>(
        text, pvwt, vb, nullptr, pv, BB*TT, CV, CT, CV, CV, 0, 0, 0);

    // 6. sim = q @ k^T per batch  (4096 x 100(->128) x 512)
    mma_gemm<0><<<dim3(1, NN_/128, BB), 256, SMEM_BYTES>>>(
        pq, pkn, nullptr, nullptr, ps, NN_, TPAD, CT, TT, TT,
        (long)NN_*CT, (long)TPAD*CT, (long)NN_*TT);

    // 7. top-5 + softmax + gather + gate + residual -> g_y
    topk_combine_kernel<<<ROWS/8, 256>>>(lscale, alpha);

    // 8. LN2
    ln2_kernel<<<ROWS, 256>>>(ln2_g, ln2_b);

    // 9. h = gelu(y2 @ w1 + b1)   (32768 x 1024 x 256)
    mma_gemm<1><<<dim3(4*CV/128, ROWS/128, 1), 256, SMEM_BYTES>>>(
        py2, pw1t, b1, nullptr, ph, ROWS, 4*CV, CV, 4*CV, 4*CV, 0, 0, 0);

    // 10. out = y2 + h @ w2 + b2   (32768 x 256 x 1024)
    mma_gemm<2><<<dim3(CV/128, ROWS/128, 1), 256, SMEM_BYTES>>>(
        ph, pw2t, b2, py2, out, ROWS, CV, 4*CV, CV, CV, 0, 0, 0);
}

// round 6
// speedup vs baseline: 3.1236x; 1.3705x over previous
#include <cuda_runtime.h>
#include <math.h>
#include <cstdint>

// ---------------------------------------------------------------------------
// Problem constants
// ---------------------------------------------------------------------------
#define BB   8
#define CV   256
#define CT   512
#define TT   100
#define TPAD 128            // padded text rows for sim GEMM
#define NN_  4096           // H*W
#define ROWS (BB*NN_)       // 32768
#define TOPM 5

// ---------------------------------------------------------------------------
// Scratch (static device globals: allocation-free)
// ---------------------------------------------------------------------------
__device__ float g_x   [ROWS * CV];        // ln1 output (fp32, residual path)
__device__ float g_xt  [ROWS * CV];        // ln1 output (tf32-rounded, GEMM A)
__device__ float g_gate[ROWS];             // sigmoid gate
__device__ float g_q   [ROWS * CT];        // x@qw+qb (tf32-rounded)
__device__ float g_qinv[ROWS];             // 1/||q row||
__device__ float g_kn  [BB * TPAD * CT];   // l2norm(text) rounded, padded
__device__ float g_tr  [BB * TT * CT];     // text rounded (V GEMM A)
__device__ float g_v   [BB * TT * CV];     // text@vw+vb (fp32)
__device__ int   g_pad [BB * TT];
__device__ float g_sim [ROWS * TT];        // q_norm . k
__device__ float g_y2  [ROWS * CV];        // ln2 output (fp32, residual)
__device__ float g_y2t [ROWS * CV];        // ln2 output (rounded, GEMM A)
__device__ float g_h   [ROWS * 4 * CV];    // gelu hidden (rounded)
// transposed + rounded weights ([N,K] K-major)
__device__ float g_qwt [CT * CV];
__device__ float g_vwt [CV * CT];
__device__ float g_w1t [4*CV * CV];
__device__ float g_w2t [CV * 4*CV];

// ---------------------------------------------------------------------------
// PTX helpers
// ---------------------------------------------------------------------------
__device__ __forceinline__ uint32_t smem_to_u32(const void* p) {
    uint32_t a;
    asm("{ .reg .u64 t; cvta.to.shared.u64 t, %1; cvt.u32.u64 %0, t; }"
        : "=r"(a) : "l"(p));
    return a;
}
__device__ __forceinline__ void cp16(uint32_t dst, const float* src, bool pred) {
    int sz = pred ? 16 : 0;
    asm volatile("cp.async.cg.shared.global [%0], [%1], 16, %2;\n"
        :: "r"(dst), "l"(src), "r"(sz));
}
__device__ __forceinline__ float tf32r(float x) {   // round-to-nearest tf32, as fp32 bits
    uint32_t u;
    asm("cvt.rna.tf32.f32 %0, %1;" : "=r"(u) : "f"(x));
    return __uint_as_float(u);
}
__device__ __forceinline__ void mma8(float* c, const uint32_t* a, const uint32_t* b) {
    asm volatile(
        "mma.sync.aligned.m16n8k8.row.col.f32.tf32.tf32.f32 "
        "{%0,%1,%2,%3},{%4,%5,%6,%7},{%8,%9},{%0,%1,%2,%3};"
        : "+f"(c[0]), "+f"(c[1]), "+f"(c[2]), "+f"(c[3])
        : "r"(a[0]), "r"(a[1]), "r"(a[2]), "r"(a[3]), "r"(b[0]), "r"(b[1]));
}
__device__ __forceinline__ void ldsm4(uint32_t* r, uint32_t addr) {
    asm volatile("ldmatrix.sync.aligned.m8n8.x4.shared.b16 {%0,%1,%2,%3}, [%4];"
        : "=r"(r[0]), "=r"(r[1]), "=r"(r[2]), "=r"(r[3]) : "r"(addr));
}
__device__ __forceinline__ float wred(float v) {
    #pragma unroll
    for (int o = 16; o; o >>= 1) v += __shfl_xor_sync(0xffffffffu, v, o);
    return v;
}

// ---------------------------------------------------------------------------
// Warp-per-row elementwise kernels (256 thr = 8 warps/block)
// ---------------------------------------------------------------------------
__global__ void ln1_gate_kernel(const float* __restrict__ vis,
                                const float* __restrict__ g, const float* __restrict__ b,
                                const float* __restrict__ gw, const float* __restrict__ gb) {
    int row = blockIdx.x * 8 + (threadIdx.x >> 5);
    int lane = threadIdx.x & 31;
    const float4* vr = (const float4*)(vis + (long)row * CV);
    float4 v0 = vr[lane * 2], v1 = vr[lane * 2 + 1];
    float s = v0.x + v0.y + v0.z + v0.w + v1.x + v1.y + v1.z + v1.w;
    float mean = wred(s) * (1.f / CV);
    float d[8] = {v0.x-mean, v0.y-mean, v0.z-mean, v0.w-mean,
                  v1.x-mean, v1.y-mean, v1.z-mean, v1.w-mean};
    float sq = 0.f;
    #pragma unroll
    for (int e = 0; e < 8; e++) sq += d[e] * d[e];
    float rs = rsqrtf(wred(sq) * (1.f / CV) + 1e-5f);
    const float4* gr = (const float4*)g;  const float4* br = (const float4*)b;
    const float4* gwr = (const float4*)gw;
    float4 ga = gr[lane*2], gb4 = gr[lane*2+1], ba = br[lane*2], bb4 = br[lane*2+1];
    float4 wa = gwr[lane*2], wb = gwr[lane*2+1];
    float xv[8];
    xv[0]=d[0]*rs*ga.x+ba.x; xv[1]=d[1]*rs*ga.y+ba.y; xv[2]=d[2]*rs*ga.z+ba.z; xv[3]=d[3]*rs*ga.w+ba.w;
    xv[4]=d[4]*rs*gb4.x+bb4.x; xv[5]=d[5]*rs*gb4.y+bb4.y; xv[6]=d[6]*rs*gb4.z+bb4.z; xv[7]=d[7]*rs*gb4.w+bb4.w;
    float4* xo  = (float4*)(g_x  + (long)row * CV);
    float4* xto = (float4*)(g_xt + (long)row * CV);
    xo[lane*2]   = make_float4(xv[0],xv[1],xv[2],xv[3]);
    xo[lane*2+1] = make_float4(xv[4],xv[5],xv[6],xv[7]);
    xto[lane*2]   = make_float4(tf32r(xv[0]),tf32r(xv[1]),tf32r(xv[2]),tf32r(xv[3]));
    xto[lane*2+1] = make_float4(tf32r(xv[4]),tf32r(xv[5]),tf32r(xv[6]),tf32r(xv[7]));
    float gp = xv[0]*wa.x+xv[1]*wa.y+xv[2]*wa.z+xv[3]*wa.w
             + xv[4]*wb.x+xv[5]*wb.y+xv[6]*wb.z+xv[7]*wb.w;
    gp = wred(gp);
    if (lane == 0) g_gate[row] = 1.f / (1.f + expf(-(gp + gb[0])));
}

__global__ void qnorm_kernel() {
    int row = blockIdx.x * 8 + (threadIdx.x >> 5);
    int lane = threadIdx.x & 31;
    const float4* qr = (const float4*)(g_q + (long)row * CT);
    float ss = 0.f;
    #pragma unroll
    for (int j = 0; j < 4; j++) {
        float4 v = qr[lane + j * 32];
        ss += v.x*v.x + v.y*v.y + v.z*v.z + v.w*v.w;
    }
    ss = wred(ss);
    if (lane == 0) g_qinv[row] = 1.f / fmaxf(sqrtf(ss), 1e-6f);
}

// k = l2norm(text) rounded into padded [BB][TPAD][CT]; pad flags; rounded text copy
__global__ void text_prep_kernel(const float* __restrict__ text) {
    int p = blockIdx.x * 8 + (threadIdx.x >> 5);
    int lane = threadIdx.x & 31;
    int b = p >> 7, t = p & (TPAD - 1);
    float4* ko = (float4*)(g_kn + (long)p * CT);
    if (t >= TT) {
        #pragma unroll
        for (int j = 0; j < 4; j++) ko[lane + j * 32] = make_float4(0,0,0,0);
        return;
    }
    const float4* tr = (const float4*)(text + ((long)b * TT + t) * CT);
    float4* tro = (float4*)(g_tr + ((long)b * TT + t) * CT);
    float4 v[4]; float sa = 0.f, ss = 0.f;
    #pragma unroll
    for (int j = 0; j < 4; j++) {
        v[j] = tr[lane + j * 32];
        sa += fabsf(v[j].x)+fabsf(v[j].y)+fabsf(v[j].z)+fabsf(v[j].w);
        ss += v[j].x*v[j].x + v[j].y*v[j].y + v[j].z*v[j].z + v[j].w*v[j].w;
    }
    sa = wred(sa); ss = wred(ss);
    if (lane == 0) g_pad[b * TT + t] = (sa <= 1e-6f) ? 1 : 0;
    float inv = 1.f / fmaxf(sqrtf(ss), 1e-6f);
    #pragma unroll
    for (int j = 0; j < 4; j++) {
        ko[lane + j * 32] = make_float4(tf32r(v[j].x*inv), tf32r(v[j].y*inv),
                                        tf32r(v[j].z*inv), tf32r(v[j].w*inv));
        tro[lane + j * 32] = make_float4(tf32r(v[j].x), tf32r(v[j].y),
                                         tf32r(v[j].z), tf32r(v[j].w));
    }
}

// 32x32 tiled transpose with tf32 rounding: dst[n*K+k] = round(src[k*N+n])
__global__ void transpose_kernel(const float* __restrict__ src, float* __restrict__ dst,
                                 int Kd, int Nd) {
    __shared__ float t[32][33];
    int k0 = blockIdx.y * 32, n0 = blockIdx.x * 32;
    int x = threadIdx.x, y = threadIdx.y;
    #pragma unroll
    for (int i = 0; i < 32; i += 8)
        t[y + i][x] = src[(long)(k0 + y + i) * Nd + n0 + x];
    __syncthreads();
    #pragma unroll
    for (int i = 0; i < 32; i += 8)
        dst[(long)(n0 + y + i) * Kd + k0 + x] = tf32r(t[x][y + i]);
}

// ---------------------------------------------------------------------------
// tf32 mma.sync GEMM with ldmatrix fragments (inputs pre-rounded).
//   EPI 0: +bias                    1: +bias, GELU, round (MLP1 -> g_h)
//   EPI 2: +bias, +residual R       3: row-scale by R[m] (sim)
//   EPI 4: +bias, round (Q GEMM)
// CTA 128x128, BK=32, 8 warps (2x4), warp 64x32, 2-stage cp.async.
// ---------------------------------------------------------------------------
#define SPITCH 36
#define TILE_F (128 * SPITCH)
#define STAGE_F (2 * TILE_F)
#define SMEM_BYTES (2 * STAGE_F * 4)

template<int EPI>
__global__ __launch_bounds__(256, 2) void mma_gemm(
    const float* __restrict__ A, const float* __restrict__ Bt,
    const float* __restrict__ bias, const float* __restrict__ R,
    float* __restrict__ C, int M, int N, int K,
    int ldc, int n_store, long sA, long sB, long sC)
{
    extern __shared__ float smem[];
    uint32_t sbase = smem_to_u32(smem);

    A  += (long)blockIdx.z * sA;
    Bt += (long)blockIdx.z * sB;
    C  += (long)blockIdx.z * sC;
    const float* Rp = (EPI == 2) ? (R + (long)blockIdx.z * sC) : R;

    int tid = threadIdx.x, wid = tid >> 5, lane = tid & 31;
    int wm = wid & 1, wn = wid >> 1;
    int lr = lane >> 2, lc = lane & 3;
    int m0 = blockIdx.y * 128, n0 = blockIdx.x * 128;

    // ldmatrix lane address components
    int sel = lane >> 3, l8 = lane & 7;
    uint32_t aOff = (uint32_t)(((wm * 64 + (sel & 1) * 8 + l8) * SPITCH + (sel >> 1) * 4) * 4);
    uint32_t bOff = (uint32_t)(((wn * 32 + (sel >> 1) * 8 + l8) * SPITCH + (sel & 1) * 4) * 4);

    float acc[4][4][4];
    #pragma unroll
    for (int i = 0; i < 4; i++)
        #pragma unroll
        for (int j = 0; j < 4; j++)
            #pragma unroll
            for (int e = 0; e < 4; e++) acc[i][j][e] = 0.f;

    int nc = K >> 5;

    auto load_chunk = [&](int buf, int kc) {
        uint32_t a_s = sbase + (uint32_t)(buf * STAGE_F) * 4u;
        uint32_t b_s = a_s + (uint32_t)TILE_F * 4u;
        long koff = (long)kc * 32;
        #pragma unroll
        for (int i = 0; i < 4; i++) {
            int p = tid + 256 * i;
            int r = p >> 3, k4 = (p & 7) * 4;
            uint32_t off = (uint32_t)(r * SPITCH + k4) * 4u;
            cp16(a_s + off, A + (long)(m0 + r) * K + koff + k4, (m0 + r) < M);
        }
        #pragma unroll
        for (int i = 0; i < 4; i++) {
            int p = tid + 256 * i;
            int r = p >> 3, k4 = (p & 7) * 4;
            uint32_t off = (uint32_t)(r * SPITCH + k4) * 4u;
            cp16(b_s + off, Bt + (long)(n0 + r) * K + koff + k4, (n0 + r) < N);
        }
        asm volatile("cp.async.commit_group;\n" ::: "memory");
    };

    load_chunk(0, 0);
    if (nc > 1) load_chunk(1, 1);

    for (int c = 0; c < nc; c++) {
        int buf = c & 1;
        if (c == nc - 1) asm volatile("cp.async.wait_group 0;\n" ::: "memory");
        else             asm volatile("cp.async.wait_group 1;\n" ::: "memory");
        __syncthreads();

        uint32_t aBase = sbase + (uint32_t)(buf * STAGE_F) * 4u + aOff;
        uint32_t bBase = sbase + (uint32_t)(buf * STAGE_F + TILE_F) * 4u + bOff;

        #pragma unroll
        for (int ks = 0; ks < 4; ks++) {
            uint32_t kbyte = (uint32_t)(ks * 8 * 4);
            uint32_t af[4][4], bf[2][4];
            #pragma unroll
            for (int mi = 0; mi < 4; mi++)
                ldsm4(af[mi], aBase + (uint32_t)(mi * 16 * SPITCH * 4) + kbyte);
            #pragma unroll
            for (int np = 0; np < 2; np++)
                ldsm4(bf[np], bBase + (uint32_t)(np * 16 * SPITCH * 4) + kbyte);
            #pragma unroll
            for (int mi = 0; mi < 4; mi++)
                #pragma unroll
                for (int ni = 0; ni < 4; ni++)
                    mma8(acc[mi][ni], af[mi], &bf[ni >> 1][(ni & 1) * 2]);
        }
        __syncthreads();
        if (c + 2 < nc) load_chunk(buf, c + 2);
    }

    // ---- epilogue ----
    #pragma unroll
    for (int mi = 0; mi < 4; mi++) {
        #pragma unroll
        for (int half = 0; half < 2; half++) {
            int m = m0 + wm * 64 + mi * 16 + lr + half * 8;
            if (m >= M) continue;
            float rscale = (EPI == 3) ? Rp[m] : 0.f;
            #pragma unroll
            for (int ni = 0; ni < 4; ni++) {
                int n = n0 + wn * 32 + ni * 8 + 2 * lc;
                #pragma unroll
                for (int e = 0; e < 2; e++) {
                    int ne = n + e;
                    if (ne >= n_store) continue;
                    float x = acc[mi][ni][half * 2 + e];
                    if (EPI != 3 && bias) x += bias[ne];
                    if (EPI == 1) { x = 0.5f * x * (1.f + erff(x * 0.70710678118654752f)); x = tf32r(x); }
                    if (EPI == 2) x += Rp[(long)m * ldc + ne];
                    if (EPI == 3) x *= rscale;
                    if (EPI == 4) x = tf32r(x);
                    C[(long)m * ldc + ne] = x;
                }
            }
        }
    }
}

// ---------------------------------------------------------------------------
// top-5 + softmax + gather + gate + residual + fused LN2 (one warp per pixel)
// writes g_y2 (fp32) and g_y2t (tf32-rounded)
// ---------------------------------------------------------------------------
__global__ void topk_ln2_kernel(const float* __restrict__ logit_scale,
                                const float* __restrict__ alpha_p,
                                const float* __restrict__ g2,
                                const float* __restrict__ b2) {
    int warp = (blockIdx.x * blockDim.x + threadIdx.x) >> 5;
    int lane = threadIdx.x & 31;
    int b = warp >> 12;

    float ls = logit_scale[0];
    float scale = expf(fminf(fmaxf(ls, -2.f), 2.f)) * rsqrtf((float)CT);
    float alpha = alpha_p[0];

    const float* srow = g_sim + (long)warp * TT;
    float vals[4]; int idxs[4];
    #pragma unroll
    for (int i = 0; i < 4; i++) {
        int t = lane + 32 * i;
        if (t < TT) { vals[i] = srow[t] * scale; idxs[i] = t; }
        else        { vals[i] = -INFINITY;       idxs[i] = 0x7fffffff; }
    }

    float wv[TOPM]; int wi[TOPM];
    #pragma unroll
    for (int m = 0; m < TOPM; m++) {
        float bv = vals[0]; int bi = idxs[0];
        #pragma unroll
        for (int i = 1; i < 4; i++)
            if (vals[i] > bv || (vals[i] == bv && idxs[i] < bi)) { bv = vals[i]; bi = idxs[i]; }
        float rv = bv; int ri = bi;
        #pragma unroll
        for (int off = 16; off; off >>= 1) {
            float ov = __shfl_xor_sync(0xffffffffu, rv, off);
            int   oi = __shfl_xor_sync(0xffffffffu, ri, off);
            if (ov > rv || (ov == rv && oi < ri)) { rv = ov; ri = oi; }
        }
        wv[m] = rv; wi[m] = ri;
        if ((ri & 31) == lane) {
            int s = ri >> 5;
            vals[s] = -INFINITY; idxs[s] = 0x7fffffff;
        }
    }

    float mx = -INFINITY;
    #pragma unroll
    for (int m = 0; m < TOPM; m++) {
        if (g_pad[b * TT + wi[m]]) wv[m] = -INFINITY;
        mx = fmaxf(mx, wv[m]);
    }
    float e[TOPM]; float se = 0.f;
    #pragma unroll
    for (int m = 0; m < TOPM; m++) {
        e[m] = (wv[m] == -INFINITY) ? 0.f : expf(wv[m] - mx);
        se += e[m];
    }
    float inv = 1.f / se;
    float ag = alpha * g_gate[warp];

    long rowoff = (long)warp * CV;
    float yv[8];
    #pragma unroll
    for (int j = 0; j < 8; j++) {
        int c = lane + 32 * j;
        float acc = 0.f;
        #pragma unroll
        for (int m = 0; m < TOPM; m++)
            acc = fmaf(e[m] * inv, g_v[(long)(b * TT + wi[m]) * CV + c], acc);
        yv[j] = g_x[rowoff + c] + ag * acc;
    }
    // fused LayerNorm2 over the 256 values held by this warp
    float s = 0.f;
    #pragma unroll
    for (int j = 0; j < 8; j++) s += yv[j];
    float mean = wred(s) * (1.f / CV);
    float sq = 0.f;
    #pragma unroll
    for (int j = 0; j < 8; j++) { float d = yv[j] - mean; sq += d * d; }
    float rs = rsqrtf(wred(sq) * (1.f / CV) + 1e-5f);
    #pragma unroll
    for (int j = 0; j < 8; j++) {
        int c = lane + 32 * j;
        float y2 = (yv[j] - mean) * rs * g2[c] + b2[c];
        g_y2 [rowoff + c] = y2;
        g_y2t[rowoff + c] = tf32r(y2);
    }
}

// ---------------------------------------------------------------------------
// Launch
// ---------------------------------------------------------------------------
static float* symaddr(const void* sym) {
    void* p = nullptr;
    cudaGetSymbolAddress(&p, sym);
    return (float*)p;
}

extern "C" void kernel_launch(void* const* d_in, const int* in_sizes, int n_in,
                              void* d_out, int out_size) {
    const float* visual = (const float*)d_in[0];
    const float* text   = (const float*)d_in[1];
    const float* ln1_g  = (const float*)d_in[2];
    const float* ln1_b  = (const float*)d_in[3];
    const float* qw     = (const float*)d_in[4];
    const float* qb     = (const float*)d_in[5];
    const float* vw     = (const float*)d_in[6];
    const float* vb     = (const float*)d_in[7];
    const float* gate_w = (const float*)d_in[8];
    const float* gate_b = (const float*)d_in[9];
    const float* lscale = (const float*)d_in[10];
    const float* alpha  = (const float*)d_in[11];
    const float* ln2_g  = (const float*)d_in[12];
    const float* ln2_b  = (const float*)d_in[13];
    const float* w1     = (const float*)d_in[14];
    const float* b1     = (const float*)d_in[15];
    const float* w2     = (const float*)d_in[16];
    const float* b2     = (const float*)d_in[17];
    float* out = (float*)d_out;

    float* pxt  = symaddr(g_xt);
    float* pq   = symaddr(g_q);
    float* pqin = symaddr(g_qinv);
    float* pkn  = symaddr(g_kn);
    float* ptr  = symaddr(g_tr);
    float* pv   = symaddr(g_v);
    float* ps   = symaddr(g_sim);
    float* py2  = symaddr(g_y2);
    float* py2t = symaddr(g_y2t);
    float* ph   = symaddr(g_h);
    float* pqwt = symaddr(g_qwt);
    float* pvwt = symaddr(g_vwt);
    float* pw1t = symaddr(g_w1t);
    float* pw2t = symaddr(g_w2t);

    cudaFuncSetAttribute(mma_gemm<0>, cudaFuncAttributeMaxDynamicSharedMemorySize, SMEM_BYTES);
    cudaFuncSetAttribute(mma_gemm<1>, cudaFuncAttributeMaxDynamicSharedMemorySize, SMEM_BYTES);
    cudaFuncSetAttribute(mma_gemm<2>, cudaFuncAttributeMaxDynamicSharedMemorySize, SMEM_BYTES);
    cudaFuncSetAttribute(mma_gemm<3>, cudaFuncAttributeMaxDynamicSharedMemorySize, SMEM_BYTES);
    cudaFuncSetAttribute(mma_gemm<4>, cudaFuncAttributeMaxDynamicSharedMemorySize, SMEM_BYTES);

    // 0. weight transposes (rounded)
    transpose_kernel<<<dim3(CT/32, CV/32), dim3(32,8)>>>(qw, pqwt, CV, CT);
    transpose_kernel<<<dim3(CV/32, CT/32), dim3(32,8)>>>(vw, pvwt, CT, CV);
    transpose_kernel<<<dim3(4*CV/32, CV/32), dim3(32,8)>>>(w1, pw1t, CV, 4*CV);
    transpose_kernel<<<dim3(CV/32, 4*CV/32), dim3(32,8)>>>(w2, pw2t, 4*CV, CV);

    // 1. LN1 + gate (warp per row)
    ln1_gate_kernel<<<ROWS/8, 256>>>(visual, ln1_g, ln1_b, gate_w, gate_b);

    // 2. Q = x @ qw + qb, rounded  (32768 x 512 x 256)
    mma_gemm<4><<<dim3(CT/128, ROWS/128, 1), 256, SMEM_BYTES>>>(
        pxt, pqwt, qb, nullptr, pq, ROWS, CT, CV, CT, CT, 0, 0, 0);

    // 3. row inv-norms of q
    qnorm_kernel<<<ROWS/8, 256>>>();

    // 4. k-norm (rounded, padded) + pad flags + rounded text copy
    text_prep_kernel<<<BB * TPAD / 8, 256>>>(text);

    // 5. V = text @ vw + vb   (800 x 256 x 512)
    mma_gemm<0><<<dim3(CV/128, (BB*TT + 127)/128, 1), 256, SMEM_BYTES>>>(
        ptr, pvwt, vb, nullptr, pv, BB*TT, CV, CT, CV, CV, 0, 0, 0);

    // 6. sim = (q @ k^T) * inv_norm[m], per batch  (4096 x 100(->128) x 512)
    mma_gemm<3><<<dim3(1, NN_/128, BB), 256, SMEM_BYTES>>>(
        pq, pkn, nullptr, pqin, ps, NN_, TPAD, CT, TT, TT,
        (long)NN_*CT, (long)TPAD*CT, (long)NN_*TT);

    // 7. top-5 + softmax + gather + gate + residual + LN2 -> g_y2, g_y2t
    topk_ln2_kernel<<<ROWS/8, 256>>>(lscale, alpha, ln2_g, ln2_b);

    // 8. h = gelu(y2 @ w1 + b1), rounded   (32768 x 1024 x 256)
    mma_gemm<1><<<dim3(4*CV/128, ROWS/128, 1), 256, SMEM_BYTES>>>(
        py2t, pw1t, b1, nullptr, ph, ROWS, 4*CV, CV, 4*CV, 4*CV, 0, 0, 0);

    // 9. out = y2 + h @ w2 + b2   (32768 x 256 x 1024)
    mma_gemm<2><<<dim3(CV/128, ROWS/128, 1), 256, SMEM_BYTES>>>(
        ph, pw2t, b2, py2, out, ROWS, CV, 4*CV, CV, CV, 0, 0, 0);
}

// round 9
// speedup vs baseline: 4.5203x; 1.4471x over previous
#include <cuda_runtime.h>
#include <cuda_fp16.h>
#include <math.h>
#include <cstdint>

// ---------------------------------------------------------------------------
// Problem constants
// ---------------------------------------------------------------------------
#define BB   8
#define CV   256
#define CT   512
#define TT   100
#define TPAD 128            // padded text rows for sim GEMM
#define NN_  4096           // H*W
#define ROWS (BB*NN_)       // 32768
#define TOPM 5

// ---------------------------------------------------------------------------
// Scratch (static device globals: allocation-free)
// ---------------------------------------------------------------------------
__device__ float  g_x   [ROWS * CV];        // ln1 output (fp32, residual path)
__device__ __half g_xt  [ROWS * CV];        // ln1 output (fp16, GEMM A)
__device__ float  g_gate[ROWS];             // sigmoid gate
__device__ __half g_q   [ROWS * CT];        // x@qw+qb (fp16)
__device__ float  g_qinv[ROWS];             // 1/||q row||
__device__ __half g_kn  [BB * TPAD * CT];   // l2norm(text) fp16, padded
__device__ __half g_tr  [BB * TT * CT];     // text fp16 (V GEMM A)
__device__ float  g_v   [BB * TT * CV];     // text@vw+vb (fp32)
__device__ int    g_pad [BB * TT];
__device__ float  g_sim [ROWS * TT];        // q_norm . k
__device__ float  g_y2  [ROWS * CV];        // ln2 output (fp32, residual)
__device__ __half g_y2t [ROWS * CV];        // ln2 output (fp16, GEMM A)
__device__ __half g_h   [ROWS * 4 * CV];    // gelu hidden (fp16)
// transposed fp16 weights ([N,K] K-major)
__device__ __half g_qwt [CT * CV];
__device__ __half g_vwt [CV * CT];
__device__ __half g_w1t [4*CV * CV];
__device__ __half g_w2t [CV * 4*CV];

// ---------------------------------------------------------------------------
// PTX helpers
// ---------------------------------------------------------------------------
__device__ __forceinline__ uint32_t smem_to_u32(const void* p) {
    uint32_t a;
    asm("{ .reg .u64 t; cvta.to.shared.u64 t, %1; cvt.u32.u64 %0, t; }"
        : "=r"(a) : "l"(p));
    return a;
}
__device__ __forceinline__ void cp16(uint32_t dst, const void* src, bool pred) {
    int sz = pred ? 16 : 0;
    asm volatile("cp.async.cg.shared.global [%0], [%1], 16, %2;\n"
        :: "r"(dst), "l"(src), "r"(sz));
}
__device__ __forceinline__ void mma16(float* c, const uint32_t* a, const uint32_t* b) {
    asm volatile(
        "mma.sync.aligned.m16n8k16.row.col.f32.f16.f16.f32 "
        "{%0,%1,%2,%3},{%4,%5,%6,%7},{%8,%9},{%0,%1,%2,%3};"
        : "+f"(c[0]), "+f"(c[1]), "+f"(c[2]), "+f"(c[3])
        : "r"(a[0]), "r"(a[1]), "r"(a[2]), "r"(a[3]), "r"(b[0]), "r"(b[1]));
}
__device__ __forceinline__ void ldsm4(uint32_t* r, uint32_t addr) {
    asm volatile("ldmatrix.sync.aligned.m8n8.x4.shared.b16 {%0,%1,%2,%3}, [%4];"
        : "=r"(r[0]), "=r"(r[1]), "=r"(r[2]), "=r"(r[3]) : "r"(addr));
}
__device__ __forceinline__ float wred(float v) {
    #pragma unroll
    for (int o = 16; o; o >>= 1) v += __shfl_xor_sync(0xffffffffu, v, o);
    return v;
}

// ---------------------------------------------------------------------------
// Warp-per-row elementwise kernels (256 thr = 8 warps/block)
// ---------------------------------------------------------------------------
__global__ void ln1_gate_kernel(const float* __restrict__ vis,
                                const float* __restrict__ g, const float* __restrict__ b,
                                const float* __restrict__ gw, const float* __restrict__ gbp) {
    int row = blockIdx.x * 8 + (threadIdx.x >> 5);
    int lane = threadIdx.x & 31;
    const float4* vr = (const float4*)(vis + (long)row * CV);
    float4 v0 = vr[lane * 2], v1 = vr[lane * 2 + 1];
    float s = v0.x + v0.y + v0.z + v0.w + v1.x + v1.y + v1.z + v1.w;
    float mean = wred(s) * (1.f / CV);
    float d[8] = {v0.x-mean, v0.y-mean, v0.z-mean, v0.w-mean,
                  v1.x-mean, v1.y-mean, v1.z-mean, v1.w-mean};
    float sq = 0.f;
    #pragma unroll
    for (int e = 0; e < 8; e++) sq += d[e] * d[e];
    float rs = rsqrtf(wred(sq) * (1.f / CV) + 1e-5f);
    const float4* gr = (const float4*)g;  const float4* br = (const float4*)b;
    const float4* gwr = (const float4*)gw;
    float4 ga = gr[lane*2], gb4 = gr[lane*2+1], ba = br[lane*2], bb4 = br[lane*2+1];
    float4 wa = gwr[lane*2], wb = gwr[lane*2+1];
    float xv[8];
    xv[0]=d[0]*rs*ga.x+ba.x; xv[1]=d[1]*rs*ga.y+ba.y; xv[2]=d[2]*rs*ga.z+ba.z; xv[3]=d[3]*rs*ga.w+ba.w;
    xv[4]=d[4]*rs*gb4.x+bb4.x; xv[5]=d[5]*rs*gb4.y+bb4.y; xv[6]=d[6]*rs*gb4.z+bb4.z; xv[7]=d[7]*rs*gb4.w+bb4.w;
    float4* xo = (float4*)(g_x + (long)row * CV);
    xo[lane*2]   = make_float4(xv[0],xv[1],xv[2],xv[3]);
    xo[lane*2+1] = make_float4(xv[4],xv[5],xv[6],xv[7]);
    __half2* xto = (__half2*)(g_xt + (long)row * CV);
    xto[lane*4+0] = __floats2half2_rn(xv[0], xv[1]);
    xto[lane*4+1] = __floats2half2_rn(xv[2], xv[3]);
    xto[lane*4+2] = __floats2half2_rn(xv[4], xv[5]);
    xto[lane*4+3] = __floats2half2_rn(xv[6], xv[7]);
    float gp = xv[0]*wa.x+xv[1]*wa.y+xv[2]*wa.z+xv[3]*wa.w
             + xv[4]*wb.x+xv[5]*wb.y+xv[6]*wb.z+xv[7]*wb.w;
    gp = wred(gp);
    if (lane == 0) g_gate[row] = 1.f / (1.f + expf(-(gp + gbp[0])));
}

__global__ void qnorm_kernel() {
    int row = blockIdx.x * 8 + (threadIdx.x >> 5);
    int lane = threadIdx.x & 31;
    const __half2* qr = (const __half2*)(g_q + (long)row * CT);
    float ss = 0.f;
    #pragma unroll
    for (int j = 0; j < 8; j++) {
        float2 v = __half22float2(qr[lane + j * 32]);
        ss += v.x*v.x + v.y*v.y;
    }
    ss = wred(ss);
    if (lane == 0) g_qinv[row] = 1.f / fmaxf(sqrtf(ss), 1e-6f);
}

// k = l2norm(text) fp16 into padded [BB][TPAD][CT]; pad flags; fp16 text copy
__global__ void text_prep_kernel(const float* __restrict__ text) {
    int p = blockIdx.x * 8 + (threadIdx.x >> 5);
    int lane = threadIdx.x & 31;
    int b = p >> 7, t = p & (TPAD - 1);
    __half2* ko = (__half2*)(g_kn + (long)p * CT);
    if (t >= TT) {
        #pragma unroll
        for (int j = 0; j < 4; j++) {
            ko[2*(lane + j*32)]     = __floats2half2_rn(0.f, 0.f);
            ko[2*(lane + j*32) + 1] = __floats2half2_rn(0.f, 0.f);
        }
        return;
    }
    const float4* tr = (const float4*)(text + ((long)b * TT + t) * CT);
    __half2* tro = (__half2*)(g_tr + ((long)b * TT + t) * CT);
    float4 v[4]; float sa = 0.f, ss = 0.f;
    #pragma unroll
    for (int j = 0; j < 4; j++) {
        v[j] = tr[lane + j * 32];
        sa += fabsf(v[j].x)+fabsf(v[j].y)+fabsf(v[j].z)+fabsf(v[j].w);
        ss += v[j].x*v[j].x + v[j].y*v[j].y + v[j].z*v[j].z + v[j].w*v[j].w;
    }
    sa = wred(sa); ss = wred(ss);
    if (lane == 0) g_pad[b * TT + t] = (sa <= 1e-6f) ? 1 : 0;
    float inv = 1.f / fmaxf(sqrtf(ss), 1e-6f);
    #pragma unroll
    for (int j = 0; j < 4; j++) {
        ko[2*(lane + j*32)]     = __floats2half2_rn(v[j].x*inv, v[j].y*inv);
        ko[2*(lane + j*32) + 1] = __floats2half2_rn(v[j].z*inv, v[j].w*inv);
        tro[2*(lane + j*32)]     = __floats2half2_rn(v[j].x, v[j].y);
        tro[2*(lane + j*32) + 1] = __floats2half2_rn(v[j].z, v[j].w);
    }
}

// 32x32 tiled transpose to fp16: dst[n*K+k] = (half)src[k*N+n]
__global__ void transpose_kernel(const float* __restrict__ src, __half* __restrict__ dst,
                                 int Kd, int Nd) {
    __shared__ float t[32][33];
    int k0 = blockIdx.y * 32, n0 = blockIdx.x * 32;
    int x = threadIdx.x, y = threadIdx.y;
    #pragma unroll
    for (int i = 0; i < 32; i += 8)
        t[y + i][x] = src[(long)(k0 + y + i) * Nd + n0 + x];
    __syncthreads();
    #pragma unroll
    for (int i = 0; i < 32; i += 8)
        dst[(long)(n0 + y + i) * Kd + k0 + x] = __float2half_rn(t[x][y + i]);
}

// ---------------------------------------------------------------------------
// fp16 mma.sync GEMM: C = A[M,K] · Bt[N,K]^T (+bias/epilogue)
//   EPI 0: +bias -> fp32        1: +bias, GELU -> fp16
//   EPI 2: +bias +residual -> fp32 (out)   3: row-scale by R[z*M+m] -> fp32
//   EPI 4: +bias -> fp16
// CTA 128x128, BK=32, 8 warps (2x4), warp 64x32, 3-stage cp.async.
// ---------------------------------------------------------------------------
#define SPITCH 40                         // halfs per smem row (80 B, 16B-aligned)
#define TILE_H (128 * SPITCH)             // halfs per tile
#define STAGE_H (2 * TILE_H)              // A+B per stage
#define NSTAGE 3
#define SMEM_BYTES (NSTAGE * STAGE_H * 2) // 61440 bytes

template<int EPI>
__global__ __launch_bounds__(256, 2) void mma_gemm(
    const __half* __restrict__ A, const __half* __restrict__ Bt,
    const float* __restrict__ bias, const float* __restrict__ R,
    void* __restrict__ Cv, int M, int N, int K,
    int ldc, int n_store, long sA, long sB, long sC)
{
    extern __shared__ __half smem[];
    uint32_t sbase = smem_to_u32(smem);

    A  += (long)blockIdx.z * sA;
    Bt += (long)blockIdx.z * sB;
    float*  Cf = (float*)Cv  + (long)blockIdx.z * sC;
    __half* Ch = (__half*)Cv + (long)blockIdx.z * sC;
    const float* Rp = (EPI == 2) ? (R + (long)blockIdx.z * sC)
                    : (EPI == 3) ? (R + (long)blockIdx.z * M) : R;

    int tid = threadIdx.x, wid = tid >> 5, lane = tid & 31;
    int wm = wid & 1, wn = wid >> 1;
    int lr = lane >> 2, lc = lane & 3;
    int m0 = blockIdx.y * 128, n0 = blockIdx.x * 128;

    // ldmatrix lane address components
    int sel = lane >> 3, l8 = lane & 7;
    // A: group0: rows m..m+7 @k+0 | group1: rows +8 @k+0 | group2: rows m..m+7 @k+8 | group3: +8 @k+8
    uint32_t aOff = (uint32_t)(((wm * 64 + (sel & 1) * 8 + l8) * SPITCH + (sel >> 1) * 8) * 2);
    // B: group0: n..n+7 @k+0 | group1: n..n+7 @k+8 | group2: n+8.. @k+0 | group3: n+8.. @k+8
    uint32_t bOff = (uint32_t)(((wn * 32 + (sel >> 1) * 8 + l8) * SPITCH + (sel & 1) * 8) * 2);

    float acc[4][4][4];
    #pragma unroll
    for (int i = 0; i < 4; i++)
        #pragma unroll
        for (int j = 0; j < 4; j++)
            #pragma unroll
            for (int e = 0; e < 4; e++) acc[i][j][e] = 0.f;

    int nc = K >> 5;

    auto load_chunk = [&](int buf, int kc) {
        uint32_t a_s = sbase + (uint32_t)(buf * STAGE_H) * 2u;
        uint32_t b_s = a_s + (uint32_t)TILE_H * 2u;
        long koff = (long)kc * 32;
        #pragma unroll
        for (int i = 0; i < 2; i++) {
            int p = tid + 256 * i;                 // 0..511
            int r = p >> 2, k8 = (p & 3) * 8;
            uint32_t off = (uint32_t)(r * SPITCH + k8) * 2u;
            cp16(a_s + off, A + (long)(m0 + r) * K + koff + k8, (m0 + r) < M);
        }
        #pragma unroll
        for (int i = 0; i < 2; i++) {
            int p = tid + 256 * i;
            int r = p >> 2, k8 = (p & 3) * 8;
            uint32_t off = (uint32_t)(r * SPITCH + k8) * 2u;
            cp16(b_s + off, Bt + (long)(n0 + r) * K + koff + k8, (n0 + r) < N);
        }
        asm volatile("cp.async.commit_group;\n" ::: "memory");
    };

    load_chunk(0, 0);
    load_chunk(1, 1);
    load_chunk(2, 2);

    for (int c = 0; c < nc; c++) {
        int buf = c % NSTAGE;
        asm volatile("cp.async.wait_group 2;\n" ::: "memory");
        __syncthreads();

        uint32_t aBase = sbase + (uint32_t)(buf * STAGE_H) * 2u + aOff;
        uint32_t bBase = sbase + (uint32_t)(buf * STAGE_H + TILE_H) * 2u + bOff;

        #pragma unroll
        for (int ks = 0; ks < 2; ks++) {
            uint32_t kbyte = (uint32_t)(ks * 16 * 2);
            uint32_t af[4][4], bf[2][4];
            #pragma unroll
            for (int mi = 0; mi < 4; mi++)
                ldsm4(af[mi], aBase + (uint32_t)(mi * 16 * SPITCH * 2) + kbyte);
            #pragma unroll
            for (int np = 0; np < 2; np++)
                ldsm4(bf[np], bBase + (uint32_t)(np * 16 * SPITCH * 2) + kbyte);
            #pragma unroll
            for (int mi = 0; mi < 4; mi++)
                #pragma unroll
                for (int ni = 0; ni < 4; ni++)
                    mma16(acc[mi][ni], af[mi], &bf[ni >> 1][(ni & 1) * 2]);
        }
        __syncthreads();
        if (c + NSTAGE < nc) load_chunk(buf, c + NSTAGE);
        else asm volatile("cp.async.commit_group;\n" ::: "memory");
    }

    // ---- epilogue ----
    #pragma unroll
    for (int mi = 0; mi < 4; mi++) {
        #pragma unroll
        for (int half_ = 0; half_ < 2; half_++) {
            int m = m0 + wm * 64 + mi * 16 + lr + half_ * 8;
            if (m >= M) continue;
            float rscale = (EPI == 3) ? Rp[m] : 0.f;
            #pragma unroll
            for (int ni = 0; ni < 4; ni++) {
                int n = n0 + wn * 32 + ni * 8 + 2 * lc;
                if (EPI == 1 || EPI == 4) {
                    // full-width fp16 outputs: paired store
                    float x0 = acc[mi][ni][half_ * 2 + 0] + bias[n];
                    float x1 = acc[mi][ni][half_ * 2 + 1] + bias[n + 1];
                    if (EPI == 1) {
                        x0 = 0.5f * x0 * (1.f + erff(x0 * 0.70710678118654752f));
                        x1 = 0.5f * x1 * (1.f + erff(x1 * 0.70710678118654752f));
                    }
                    *(__half2*)(Ch + (long)m * ldc + n) = __floats2half2_rn(x0, x1);
                } else {
                    #pragma unroll
                    for (int e = 0; e < 2; e++) {
                        int ne = n + e;
                        if (ne >= n_store) continue;
                        float x = acc[mi][ni][half_ * 2 + e];
                        if (EPI != 3 && bias) x += bias[ne];
                        if (EPI == 2) x += Rp[(long)m * ldc + ne];
                        if (EPI == 3) x *= rscale;
                        Cf[(long)m * ldc + ne] = x;
                    }
                }
            }
        }
    }
}

// ---------------------------------------------------------------------------
// top-5 + softmax + gather + gate + residual + fused LN2 (one warp per pixel)
// ---------------------------------------------------------------------------
__global__ void topk_ln2_kernel(const float* __restrict__ logit_scale,
                                const float* __restrict__ alpha_p,
                                const float* __restrict__ g2,
                                const float* __restrict__ b2) {
    int warp = (blockIdx.x * blockDim.x + threadIdx.x) >> 5;
    int lane = threadIdx.x & 31;
    int b = warp >> 12;

    float ls = logit_scale[0];
    float scale = expf(fminf(fmaxf(ls, -2.f), 2.f)) * rsqrtf((float)CT);
    float alpha = alpha_p[0];

    const float* srow = g_sim + (long)warp * TT;
    float vals[4]; int idxs[4];
    #pragma unroll
    for (int i = 0; i < 4; i++) {
        int t = lane + 32 * i;
        if (t < TT) { vals[i] = srow[t] * scale; idxs[i] = t; }
        else        { vals[i] = -INFINITY;       idxs[i] = 0x7fffffff; }
    }

    float wv[TOPM]; int wi[TOPM];
    #pragma unroll
    for (int m = 0; m < TOPM; m++) {
        float bv = vals[0]; int bi = idxs[0];
        #pragma unroll
        for (int i = 1; i < 4; i++)
            if (vals[i] > bv || (vals[i] == bv && idxs[i] < bi)) { bv = vals[i]; bi = idxs[i]; }
        float rv = bv; int ri = bi;
        #pragma unroll
        for (int off = 16; off; off >>= 1) {
            float ov = __shfl_xor_sync(0xffffffffu, rv, off);
            int   oi = __shfl_xor_sync(0xffffffffu, ri, off);
            if (ov > rv || (ov == rv && oi < ri)) { rv = ov; ri = oi; }
        }
        wv[m] = rv; wi[m] = ri;
        if ((ri & 31) == lane) {
            int s = ri >> 5;
            vals[s] = -INFINITY; idxs[s] = 0x7fffffff;
        }
    }

    float mx = -INFINITY;
    #pragma unroll
    for (int m = 0; m < TOPM; m++) {
        if (g_pad[b * TT + wi[m]]) wv[m] = -INFINITY;
        mx = fmaxf(mx, wv[m]);
    }
    float e[TOPM]; float se = 0.f;
    #pragma unroll
    for (int m = 0; m < TOPM; m++) {
        e[m] = (wv[m] == -INFINITY) ? 0.f : expf(wv[m] - mx);
        se += e[m];
    }
    float inv = 1.f / se;
    float ag = alpha * g_gate[warp];

    long rowoff = (long)warp * CV;
    float yv[8];
    #pragma unroll
    for (int j = 0; j < 8; j++) {
        int c = lane + 32 * j;
        float acc = 0.f;
        #pragma unroll
        for (int m = 0; m < TOPM; m++)
            acc = fmaf(e[m] * inv, g_v[(long)(b * TT + wi[m]) * CV + c], acc);
        yv[j] = g_x[rowoff + c] + ag * acc;
    }
    // fused LayerNorm2
    float s = 0.f;
    #pragma unroll
    for (int j = 0; j < 8; j++) s += yv[j];
    float mean = wred(s) * (1.f / CV);
    float sq = 0.f;
    #pragma unroll
    for (int j = 0; j < 8; j++) { float d = yv[j] - mean; sq += d * d; }
    float rs = rsqrtf(wred(sq) * (1.f / CV) + 1e-5f);
    #pragma unroll
    for (int j = 0; j < 8; j++) {
        int c = lane + 32 * j;
        float y2 = (yv[j] - mean) * rs * g2[c] + b2[c];
        g_y2 [rowoff + c] = y2;
        g_y2t[rowoff + c] = __float2half_rn(y2);
    }
}

// ---------------------------------------------------------------------------
// Launch
// ---------------------------------------------------------------------------
static void* symaddr(const void* sym) {
    void* p = nullptr;
    cudaGetSymbolAddress(&p, sym);
    return p;
}

extern "C" void kernel_launch(void* const* d_in, const int* in_sizes, int n_in,
                              void* d_out, int out_size) {
    const float* visual = (const float*)d_in[0];
    const float* text   = (const float*)d_in[1];
    const float* ln1_g  = (const float*)d_in[2];
    const float* ln1_b  = (const float*)d_in[3];
    const float* qw     = (const float*)d_in[4];
    const float* qb     = (const float*)d_in[5];
    const float* vw     = (const float*)d_in[6];
    const float* vb     = (const float*)d_in[7];
    const float* gate_w = (const float*)d_in[8];
    const float* gate_b = (const float*)d_in[9];
    const float* lscale = (const float*)d_in[10];
    const float* alpha  = (const float*)d_in[11];
    const float* ln2_g  = (const float*)d_in[12];
    const float* ln2_b  = (const float*)d_in[13];
    const float* w1     = (const float*)d_in[14];
    const float* b1     = (const float*)d_in[15];
    const float* w2     = (const float*)d_in[16];
    const float* b2     = (const float*)d_in[17];
    float* out = (float*)d_out;

    __half* pxt  = (__half*)symaddr(g_xt);
    __half* pq   = (__half*)symaddr(g_q);
    float*  pqin = (float*) symaddr(g_qinv);
    __half* pkn  = (__half*)symaddr(g_kn);
    __half* ptr  = (__half*)symaddr(g_tr);
    float*  pv   = (float*) symaddr(g_v);
    float*  ps   = (float*) symaddr(g_sim);
    float*  py2  = (float*) symaddr(g_y2);
    __half* py2t = (__half*)symaddr(g_y2t);
    __half* ph   = (__half*)symaddr(g_h);
    __half* pqwt = (__half*)symaddr(g_qwt);
    __half* pvwt = (__half*)symaddr(g_vwt);
    __half* pw1t = (__half*)symaddr(g_w1t);
    __half* pw2t = (__half*)symaddr(g_w2t);

    cudaFuncSetAttribute(mma_gemm<0>, cudaFuncAttributeMaxDynamicSharedMemorySize, SMEM_BYTES);
    cudaFuncSetAttribute(mma_gemm<1>, cudaFuncAttributeMaxDynamicSharedMemorySize, SMEM_BYTES);
    cudaFuncSetAttribute(mma_gemm<2>, cudaFuncAttributeMaxDynamicSharedMemorySize, SMEM_BYTES);
    cudaFuncSetAttribute(mma_gemm<3>, cudaFuncAttributeMaxDynamicSharedMemorySize, SMEM_BYTES);
    cudaFuncSetAttribute(mma_gemm<4>, cudaFuncAttributeMaxDynamicSharedMemorySize, SMEM_BYTES);

    // 0. weight transposes (fp32 -> fp16 [N][K])
    transpose_kernel<<<dim3(CT/32, CV/32), dim3(32,8)>>>(qw, pqwt, CV, CT);
    transpose_kernel<<<dim3(CV/32, CT/32), dim3(32,8)>>>(vw, pvwt, CT, CV);
    transpose_kernel<<<dim3(4*CV/32, CV/32), dim3(32,8)>>>(w1, pw1t, CV, 4*CV);
    transpose_kernel<<<dim3(CV/32, 4*CV/32), dim3(32,8)>>>(w2, pw2t, 4*CV, CV);

    // 1. LN1 + gate
    ln1_gate_kernel<<<ROWS/8, 256>>>(visual, ln1_g, ln1_b, gate_w, gate_b);

    // 2. Q = x @ qw + qb -> fp16  (32768 x 512 x 256)
    mma_gemm<4><<<dim3(CT/128, ROWS/128, 1), 256, SMEM_BYTES>>>(
        pxt, pqwt, qb, nullptr, pq, ROWS, CT, CV, CT, CT, 0, 0, 0);

    // 3. row inv-norms of q
    qnorm_kernel<<<ROWS/8, 256>>>();

    // 4. k-norm (fp16, padded) + pad flags + fp16 text copy
    text_prep_kernel<<<BB * TPAD / 8, 256>>>(text);

    // 5. V = text @ vw + vb -> fp32   (800 x 256 x 512)
    mma_gemm<0><<<dim3(CV/128, (BB*TT + 127)/128, 1), 256, SMEM_BYTES>>>(
        ptr, pvwt, vb, nullptr, pv, BB*TT, CV, CT, CV, CV, 0, 0, 0);

    // 6. sim = (q @ k^T) * qinv[b,m]  (4096 x 100(->128) x 512, batched)
    mma_gemm<3><<<dim3(1, NN_/128, BB), 256, SMEM_BYTES>>>(
        pq, pkn, nullptr, pqin, ps, NN_, TPAD, CT, TT, TT,
        (long)NN_*CT, (long)TPAD*CT, (long)NN_*TT);

    // 7. top-5 + softmax + gather + gate + residual + LN2
    topk_ln2_kernel<<<ROWS/8, 256>>>(lscale, alpha, ln2_g, ln2_b);

    // 8. h = gelu(y2 @ w1 + b1) -> fp16   (32768 x 1024 x 256)
    mma_gemm<1><<<dim3(4*CV/128, ROWS/128, 1), 256, SMEM_BYTES>>>(
        py2t, pw1t, b1, nullptr, ph, ROWS, 4*CV, CV, 4*CV, 4*CV, 0, 0, 0);

    // 9. out = y2 + h @ w2 + b2 -> fp32   (32768 x 256 x 1024)
    mma_gemm<2><<<dim3(CV/128, ROWS/128, 1), 256, SMEM_BYTES>>>(
        ph, pw2t, b2, py2, out, ROWS, CV, 4*CV, CV, CV, 0, 0, 0);
}

// round 10
// speedup vs baseline: 4.7152x; 1.0431x over previous
#include <cuda_runtime.h>
#include <cuda_fp16.h>
#include <math.h>
#include <cstdint>

// ---------------------------------------------------------------------------
// Problem constants
// ---------------------------------------------------------------------------
#define BB   8
#define CV   256
#define CT   512
#define TT   100
#define TPAD 128            // padded text rows for sim GEMM
#define NN_  4096           // H*W
#define ROWS (BB*NN_)       // 32768
#define TOPM 5

// ---------------------------------------------------------------------------
// Scratch (static device globals: allocation-free)
// ---------------------------------------------------------------------------
__device__ float  g_x   [ROWS * CV];        // ln1 output (fp32, residual path)
__device__ __half g_xt  [ROWS * CV];        // ln1 output (fp16, GEMM A)
__device__ float  g_gate[ROWS];             // sigmoid gate
__device__ __half g_q   [ROWS * CT];        // x@qw+qb (fp16)
__device__ float  g_qinv[ROWS];             // 1/||q row||
__device__ __half g_kn  [BB * TPAD * CT];   // l2norm(text) fp16, padded
__device__ __half g_tr  [BB * TT * CT];     // text fp16 (V GEMM A)
__device__ float  g_v   [BB * TT * CV];     // text@vw+vb (fp32)
__device__ int    g_pad [BB * TT];
__device__ float  g_sim [ROWS * TT];        // q.k (unnormalized q)
__device__ float  g_y2  [ROWS * CV];        // ln2 output (fp32, residual)
__device__ __half g_y2t [ROWS * CV];        // ln2 output (fp16, GEMM A)
__device__ __half g_h   [ROWS * 4 * CV];    // gelu hidden (fp16)
// transposed fp16 weights ([N,K] K-major)
__device__ __half g_qwt [CT * CV];
__device__ __half g_vwt [CV * CT];
__device__ __half g_w1t [4*CV * CV];
__device__ __half g_w2t [CV * 4*CV];

// ---------------------------------------------------------------------------
// PTX helpers
// ---------------------------------------------------------------------------
__device__ __forceinline__ uint32_t smem_to_u32(const void* p) {
    uint32_t a;
    asm("{ .reg .u64 t; cvta.to.shared.u64 t, %1; cvt.u32.u64 %0, t; }"
        : "=r"(a) : "l"(p));
    return a;
}
__device__ __forceinline__ void cp16(uint32_t dst, const void* src, bool pred) {
    int sz = pred ? 16 : 0;
    asm volatile("cp.async.cg.shared.global [%0], [%1], 16, %2;\n"
        :: "r"(dst), "l"(src), "r"(sz));
}
__device__ __forceinline__ void mma16(float* c, const uint32_t* a, const uint32_t* b) {
    asm volatile(
        "mma.sync.aligned.m16n8k16.row.col.f32.f16.f16.f32 "
        "{%0,%1,%2,%3},{%4,%5,%6,%7},{%8,%9},{%0,%1,%2,%3};"
        : "+f"(c[0]), "+f"(c[1]), "+f"(c[2]), "+f"(c[3])
        : "r"(a[0]), "r"(a[1]), "r"(a[2]), "r"(a[3]), "r"(b[0]), "r"(b[1]));
}
__device__ __forceinline__ void ldsm4(uint32_t* r, uint32_t addr) {
    asm volatile("ldmatrix.sync.aligned.m8n8.x4.shared.b16 {%0,%1,%2,%3}, [%4];"
        : "=r"(r[0]), "=r"(r[1]), "=r"(r[2]), "=r"(r[3]) : "r"(addr));
}
__device__ __forceinline__ float wred(float v) {
    #pragma unroll
    for (int o = 16; o; o >>= 1) v += __shfl_xor_sync(0xffffffffu, v, o);
    return v;
}

// ---------------------------------------------------------------------------
// Fused LN1+gate (blocks [0, ROWS/8)) and text-prep (blocks [ROWS/8, +128))
// ---------------------------------------------------------------------------
#define LN1_BLOCKS (ROWS / 8)
#define TEXT_BLOCKS (BB * TPAD / 8)

__global__ void ln1_text_kernel(const float* __restrict__ vis,
                                const float* __restrict__ text,
                                const float* __restrict__ g, const float* __restrict__ b,
                                const float* __restrict__ gw, const float* __restrict__ gbp) {
    int lane = threadIdx.x & 31;
    if (blockIdx.x < LN1_BLOCKS) {
        int row = blockIdx.x * 8 + (threadIdx.x >> 5);
        const float4* vr = (const float4*)(vis + (long)row * CV);
        float4 v0 = vr[lane * 2], v1 = vr[lane * 2 + 1];
        float s = v0.x + v0.y + v0.z + v0.w + v1.x + v1.y + v1.z + v1.w;
        float mean = wred(s) * (1.f / CV);
        float d[8] = {v0.x-mean, v0.y-mean, v0.z-mean, v0.w-mean,
                      v1.x-mean, v1.y-mean, v1.z-mean, v1.w-mean};
        float sq = 0.f;
        #pragma unroll
        for (int e = 0; e < 8; e++) sq += d[e] * d[e];
        float rs = rsqrtf(wred(sq) * (1.f / CV) + 1e-5f);
        const float4* gr = (const float4*)g;  const float4* br = (const float4*)b;
        const float4* gwr = (const float4*)gw;
        float4 ga = gr[lane*2], gb4 = gr[lane*2+1], ba = br[lane*2], bb4 = br[lane*2+1];
        float4 wa = gwr[lane*2], wb = gwr[lane*2+1];
        float xv[8];
        xv[0]=d[0]*rs*ga.x+ba.x; xv[1]=d[1]*rs*ga.y+ba.y; xv[2]=d[2]*rs*ga.z+ba.z; xv[3]=d[3]*rs*ga.w+ba.w;
        xv[4]=d[4]*rs*gb4.x+bb4.x; xv[5]=d[5]*rs*gb4.y+bb4.y; xv[6]=d[6]*rs*gb4.z+bb4.z; xv[7]=d[7]*rs*gb4.w+bb4.w;
        float4* xo = (float4*)(g_x + (long)row * CV);
        xo[lane*2]   = make_float4(xv[0],xv[1],xv[2],xv[3]);
        xo[lane*2+1] = make_float4(xv[4],xv[5],xv[6],xv[7]);
        __half2* xto = (__half2*)(g_xt + (long)row * CV);
        xto[lane*4+0] = __floats2half2_rn(xv[0], xv[1]);
        xto[lane*4+1] = __floats2half2_rn(xv[2], xv[3]);
        xto[lane*4+2] = __floats2half2_rn(xv[4], xv[5]);
        xto[lane*4+3] = __floats2half2_rn(xv[6], xv[7]);
        float gp = xv[0]*wa.x+xv[1]*wa.y+xv[2]*wa.z+xv[3]*wa.w
                 + xv[4]*wb.x+xv[5]*wb.y+xv[6]*wb.z+xv[7]*wb.w;
        gp = wred(gp);
        if (lane == 0) g_gate[row] = 1.f / (1.f + expf(-(gp + gbp[0])));
    } else {
        int p = (blockIdx.x - LN1_BLOCKS) * 8 + (threadIdx.x >> 5);
        int bz = p >> 7, t = p & (TPAD - 1);
        __half2* ko = (__half2*)(g_kn + (long)p * CT);
        if (t >= TT) {
            #pragma unroll
            for (int j = 0; j < 4; j++) {
                ko[2*(lane + j*32)]     = __floats2half2_rn(0.f, 0.f);
                ko[2*(lane + j*32) + 1] = __floats2half2_rn(0.f, 0.f);
            }
            return;
        }
        const float4* tr = (const float4*)(text + ((long)bz * TT + t) * CT);
        __half2* tro = (__half2*)(g_tr + ((long)bz * TT + t) * CT);
        float4 v[4]; float sa = 0.f, ss = 0.f;
        #pragma unroll
        for (int j = 0; j < 4; j++) {
            v[j] = tr[lane + j * 32];
            sa += fabsf(v[j].x)+fabsf(v[j].y)+fabsf(v[j].z)+fabsf(v[j].w);
            ss += v[j].x*v[j].x + v[j].y*v[j].y + v[j].z*v[j].z + v[j].w*v[j].w;
        }
        sa = wred(sa); ss = wred(ss);
        if (lane == 0) g_pad[bz * TT + t] = (sa <= 1e-6f) ? 1 : 0;
        float inv = 1.f / fmaxf(sqrtf(ss), 1e-6f);
        #pragma unroll
        for (int j = 0; j < 4; j++) {
            ko[2*(lane + j*32)]     = __floats2half2_rn(v[j].x*inv, v[j].y*inv);
            ko[2*(lane + j*32) + 1] = __floats2half2_rn(v[j].z*inv, v[j].w*inv);
            tro[2*(lane + j*32)]     = __floats2half2_rn(v[j].x, v[j].y);
            tro[2*(lane + j*32) + 1] = __floats2half2_rn(v[j].z, v[j].w);
        }
    }
}

__global__ void qnorm_kernel() {
    int row = blockIdx.x * 8 + (threadIdx.x >> 5);
    int lane = threadIdx.x & 31;
    const __half2* qr = (const __half2*)(g_q + (long)row * CT);
    float ss = 0.f;
    #pragma unroll
    for (int j = 0; j < 8; j++) {
        float2 v = __half22float2(qr[lane + j * 32]);
        ss += v.x*v.x + v.y*v.y;
    }
    ss = wred(ss);
    if (lane == 0) g_qinv[row] = 1.f / fmaxf(sqrtf(ss), 1e-6f);
}

// ---------------------------------------------------------------------------
// All 4 weight transposes in ONE launch. dst[n*K+k] = (half)src[k*N+n].
//   qw: K=256,N=512  -> 128 tiles | vw: K=512,N=256 -> 128
//   w1: K=256,N=1024 -> 256      | w2: K=1024,N=256 -> 256    (total 768)
// ---------------------------------------------------------------------------
__device__ __forceinline__ void tr_tile(const float* __restrict__ src,
                                        __half* __restrict__ dst,
                                        int Kd, int Nd, int bx, int by,
                                        float (*t)[33]) {
    int k0 = by * 32, n0 = bx * 32;
    int x = threadIdx.x, y = threadIdx.y;
    #pragma unroll
    for (int i = 0; i < 32; i += 8)
        t[y + i][x] = src[(long)(k0 + y + i) * Nd + n0 + x];
    __syncthreads();
    #pragma unroll
    for (int i = 0; i < 32; i += 8)
        dst[(long)(n0 + y + i) * Kd + k0 + x] = __float2half_rn(t[x][y + i]);
}

__global__ void transpose_all_kernel(const float* __restrict__ qw, const float* __restrict__ vw,
                                     const float* __restrict__ w1, const float* __restrict__ w2) {
    __shared__ float t[32][33];
    int id = blockIdx.x;
    if (id < 128)       tr_tile(qw, g_qwt, CV, CT, id & 15, id >> 4, t);          // 16 x 8
    else if (id < 256)  { id -= 128; tr_tile(vw, g_vwt, CT, CV, id & 7, id >> 3, t); }   // 8 x 16
    else if (id < 512)  { id -= 256; tr_tile(w1, g_w1t, CV, 4*CV, id & 31, id >> 5, t); } // 32 x 8
    else                { id -= 512; tr_tile(w2, g_w2t, 4*CV, CV, id & 7, id >> 3, t); }  // 8 x 32
}

// ---------------------------------------------------------------------------
// fp16 mma.sync GEMM: C = A[M,K] · Bt[N,K]^T (+bias/epilogue)
//   EPI 0: +bias -> fp32        1: +bias, GELU -> fp16
//   EPI 2: +bias +residual -> fp32 (out)   3: row-scale by R[z*M+m] -> fp32
//   EPI 4: +bias -> fp16
// CTA 128x128, BK=32, 8 warps (2x4), warp 64x32.
// 4-stage cp.async, ONE __syncthreads per chunk (cutlass-style).
// ---------------------------------------------------------------------------
#define SPITCH 40                         // halfs per smem row (80 B)
#define TILE_H (128 * SPITCH)
#define STAGE_H (2 * TILE_H)
#define NSTAGE 4
#define SMEM_BYTES (NSTAGE * STAGE_H * 2) // 81920 bytes

template<int EPI>
__global__ __launch_bounds__(256, 2) void mma_gemm(
    const __half* __restrict__ A, const __half* __restrict__ Bt,
    const float* __restrict__ bias, const float* __restrict__ R,
    void* __restrict__ Cv, int M, int N, int K,
    int ldc, int n_store, long sA, long sB, long sC)
{
    extern __shared__ __half smem[];
    uint32_t sbase = smem_to_u32(smem);

    A  += (long)blockIdx.z * sA;
    Bt += (long)blockIdx.z * sB;
    float*  Cf = (float*)Cv  + (long)blockIdx.z * sC;
    __half* Ch = (__half*)Cv + (long)blockIdx.z * sC;
    const float* Rp = (EPI == 2) ? (R + (long)blockIdx.z * sC)
                    : (EPI == 3) ? (R + (long)blockIdx.z * M) : R;

    int tid = threadIdx.x, wid = tid >> 5, lane = tid & 31;
    int wm = wid & 1, wn = wid >> 1;
    int lr = lane >> 2, lc = lane & 3;
    int m0 = blockIdx.y * 128, n0 = blockIdx.x * 128;

    int sel = lane >> 3, l8 = lane & 7;
    uint32_t aOff = (uint32_t)(((wm * 64 + (sel & 1) * 8 + l8) * SPITCH + (sel >> 1) * 8) * 2);
    uint32_t bOff = (uint32_t)(((wn * 32 + (sel >> 1) * 8 + l8) * SPITCH + (sel & 1) * 8) * 2);

    float acc[4][4][4];
    #pragma unroll
    for (int i = 0; i < 4; i++)
        #pragma unroll
        for (int j = 0; j < 4; j++)
            #pragma unroll
            for (int e = 0; e < 4; e++) acc[i][j][e] = 0.f;

    int nc = K >> 5;

    auto load_chunk = [&](int buf, int kc) {
        uint32_t a_s = sbase + (uint32_t)(buf * STAGE_H) * 2u;
        uint32_t b_s = a_s + (uint32_t)TILE_H * 2u;
        long koff = (long)kc * 32;
        #pragma unroll
        for (int i = 0; i < 2; i++) {
            int p = tid + 256 * i;                 // 0..511
            int r = p >> 2, k8 = (p & 3) * 8;
            uint32_t off = (uint32_t)(r * SPITCH + k8) * 2u;
            cp16(a_s + off, A + (long)(m0 + r) * K + koff + k8, (m0 + r) < M);
        }
        #pragma unroll
        for (int i = 0; i < 2; i++) {
            int p = tid + 256 * i;
            int r = p >> 2, k8 = (p & 3) * 8;
            uint32_t off = (uint32_t)(r * SPITCH + k8) * 2u;
            cp16(b_s + off, Bt + (long)(n0 + r) * K + koff + k8, (n0 + r) < N);
        }
        asm volatile("cp.async.commit_group;\n" ::: "memory");
    };

    // prologue: 3 chunks in flight
    load_chunk(0, 0);
    load_chunk(1, 1);
    load_chunk(2, 2);

    for (int c = 0; c < nc; c++) {
        int buf = c & (NSTAGE - 1);
        asm volatile("cp.async.wait_group 2;\n" ::: "memory");
        __syncthreads();   // chunk c resident; all warps done with chunk c-1

        // prefetch chunk c+3 into the buffer consumed at iteration c-1
        if (c + 3 < nc) load_chunk((c + 3) & (NSTAGE - 1), c + 3);
        else asm volatile("cp.async.commit_group;\n" ::: "memory");

        uint32_t aBase = sbase + (uint32_t)(buf * STAGE_H) * 2u + aOff;
        uint32_t bBase = sbase + (uint32_t)(buf * STAGE_H + TILE_H) * 2u + bOff;

        #pragma unroll
        for (int ks = 0; ks < 2; ks++) {
            uint32_t kbyte = (uint32_t)(ks * 16 * 2);
            uint32_t af[4][4], bf[2][4];
            #pragma unroll
            for (int mi = 0; mi < 4; mi++)
                ldsm4(af[mi], aBase + (uint32_t)(mi * 16 * SPITCH * 2) + kbyte);
            #pragma unroll
            for (int np = 0; np < 2; np++)
                ldsm4(bf[np], bBase + (uint32_t)(np * 16 * SPITCH * 2) + kbyte);
            #pragma unroll
            for (int mi = 0; mi < 4; mi++)
                #pragma unroll
                for (int ni = 0; ni < 4; ni++)
                    mma16(acc[mi][ni], af[mi], &bf[ni >> 1][(ni & 1) * 2]);
        }
    }

    // ---- epilogue ----
    #pragma unroll
    for (int mi = 0; mi < 4; mi++) {
        #pragma unroll
        for (int half_ = 0; half_ < 2; half_++) {
            int m = m0 + wm * 64 + mi * 16 + lr + half_ * 8;
            if (m >= M) continue;
            float rscale = (EPI == 3) ? Rp[m] : 0.f;
            #pragma unroll
            for (int ni = 0; ni < 4; ni++) {
                int n = n0 + wn * 32 + ni * 8 + 2 * lc;
                if (EPI == 1 || EPI == 4) {
                    float x0 = acc[mi][ni][half_ * 2 + 0] + bias[n];
                    float x1 = acc[mi][ni][half_ * 2 + 1] + bias[n + 1];
                    if (EPI == 1) {
                        x0 = 0.5f * x0 * (1.f + erff(x0 * 0.70710678118654752f));
                        x1 = 0.5f * x1 * (1.f + erff(x1 * 0.70710678118654752f));
                    }
                    *(__half2*)(Ch + (long)m * ldc + n) = __floats2half2_rn(x0, x1);
                } else {
                    #pragma unroll
                    for (int e = 0; e < 2; e++) {
                        int ne = n + e;
                        if (ne >= n_store) continue;
                        float x = acc[mi][ni][half_ * 2 + e];
                        if (EPI != 3 && bias) x += bias[ne];
                        if (EPI == 2) x += Rp[(long)m * ldc + ne];
                        if (EPI == 3) x *= rscale;
                        Cf[(long)m * ldc + ne] = x;
                    }
                }
            }
        }
    }
}

// ---------------------------------------------------------------------------
// top-5 + softmax + gather + gate + residual + fused LN2 (one warp per pixel)
// ---------------------------------------------------------------------------
__global__ void topk_ln2_kernel(const float* __restrict__ logit_scale,
                                const float* __restrict__ alpha_p,
                                const float* __restrict__ g2,
                                const float* __restrict__ b2) {
    int warp = (blockIdx.x * blockDim.x + threadIdx.x) >> 5;
    int lane = threadIdx.x & 31;
    int b = warp >> 12;

    float ls = logit_scale[0];
    float scale = expf(fminf(fmaxf(ls, -2.f), 2.f)) * rsqrtf((float)CT);
    float alpha = alpha_p[0];

    const float* srow = g_sim + (long)warp * TT;
    float vals[4]; int idxs[4];
    #pragma unroll
    for (int i = 0; i < 4; i++) {
        int t = lane + 32 * i;
        if (t < TT) { vals[i] = srow[t] * scale; idxs[i] = t; }
        else        { vals[i] = -INFINITY;       idxs[i] = 0x7fffffff; }
    }

    float wv[TOPM]; int wi[TOPM];
    #pragma unroll
    for (int m = 0; m < TOPM; m++) {
        float bv = vals[0]; int bi = idxs[0];
        #pragma unroll
        for (int i = 1; i < 4; i++)
            if (vals[i] > bv || (vals[i] == bv && idxs[i] < bi)) { bv = vals[i]; bi = idxs[i]; }
        float rv = bv; int ri = bi;
        #pragma unroll
        for (int off = 16; off; off >>= 1) {
            float ov = __shfl_xor_sync(0xffffffffu, rv, off);
            int   oi = __shfl_xor_sync(0xffffffffu, ri, off);
            if (ov > rv || (ov == rv && oi < ri)) { rv = ov; ri = oi; }
        }
        wv[m] = rv; wi[m] = ri;
        if ((ri & 31) == lane) {
            int s = ri >> 5;
            vals[s] = -INFINITY; idxs[s] = 0x7fffffff;
        }
    }

    float mx = -INFINITY;
    #pragma unroll
    for (int m = 0; m < TOPM; m++) {
        if (g_pad[b * TT + wi[m]]) wv[m] = -INFINITY;
        mx = fmaxf(mx, wv[m]);
    }
    float e[TOPM]; float se = 0.f;
    #pragma unroll
    for (int m = 0; m < TOPM; m++) {
        e[m] = (wv[m] == -INFINITY) ? 0.f : expf(wv[m] - mx);
        se += e[m];
    }
    float inv = 1.f / se;
    float ag = alpha * g_gate[warp];

    long rowoff = (long)warp * CV;
    float yv[8];
    #pragma unroll
    for (int j = 0; j < 8; j++) {
        int c = lane + 32 * j;
        float acc = 0.f;
        #pragma unroll
        for (int m = 0; m < TOPM; m++)
            acc = fmaf(e[m] * inv, g_v[(long)(b * TT + wi[m]) * CV + c], acc);
        yv[j] = g_x[rowoff + c] + ag * acc;
    }
    // fused LayerNorm2
    float s = 0.f;
    #pragma unroll
    for (int j = 0; j < 8; j++) s += yv[j];
    float mean = wred(s) * (1.f / CV);
    float sq = 0.f;
    #pragma unroll
    for (int j = 0; j < 8; j++) { float d = yv[j] - mean; sq += d * d; }
    float rs = rsqrtf(wred(sq) * (1.f / CV) + 1e-5f);
    #pragma unroll
    for (int j = 0; j < 8; j++) {
        int c = lane + 32 * j;
        float y2 = (yv[j] - mean) * rs * g2[c] + b2[c];
        g_y2 [rowoff + c] = y2;
        g_y2t[rowoff + c] = __float2half_rn(y2);
    }
}

// ---------------------------------------------------------------------------
// Launch
// ---------------------------------------------------------------------------
static void* symaddr(const void* sym) {
    void* p = nullptr;
    cudaGetSymbolAddress(&p, sym);
    return p;
}

extern "C" void kernel_launch(void* const* d_in, const int* in_sizes, int n_in,
                              void* d_out, int out_size) {
    const float* visual = (const float*)d_in[0];
    const float* text   = (const float*)d_in[1];
    const float* ln1_g  = (const float*)d_in[2];
    const float* ln1_b  = (const float*)d_in[3];
    const float* qw     = (const float*)d_in[4];
    const float* qb     = (const float*)d_in[5];
    const float* vw     = (const float*)d_in[6];
    const float* vb     = (const float*)d_in[7];
    const float* gate_w = (const float*)d_in[8];
    const float* gate_b = (const float*)d_in[9];
    const float* lscale = (const float*)d_in[10];
    const float* alpha  = (const float*)d_in[11];
    const float* ln2_g  = (const float*)d_in[12];
    const float* ln2_b  = (const float*)d_in[13];
    const float* w1     = (const float*)d_in[14];
    const float* b1     = (const float*)d_in[15];
    const float* w2     = (const float*)d_in[16];
    const float* b2     = (const float*)d_in[17];
    float* out = (float*)d_out;

    __half* pxt  = (__half*)symaddr(g_xt);
    __half* pq   = (__half*)symaddr(g_q);
    float*  pqin = (float*) symaddr(g_qinv);
    __half* pkn  = (__half*)symaddr(g_kn);
    __half* ptr  = (__half*)symaddr(g_tr);
    float*  pv   = (float*) symaddr(g_v);
    float*  ps   = (float*) symaddr(g_sim);
    float*  py2  = (float*) symaddr(g_y2);
    __half* py2t = (__half*)symaddr(g_y2t);
    __half* ph   = (__half*)symaddr(g_h);
    __half* pqwt = (__half*)symaddr(g_qwt);
    __half* pvwt = (__half*)symaddr(g_vwt);
    __half* pw1t = (__half*)symaddr(g_w1t);
    __half* pw2t = (__half*)symaddr(g_w2t);

    cudaFuncSetAttribute(mma_gemm<0>, cudaFuncAttributeMaxDynamicSharedMemorySize, SMEM_BYTES);
    cudaFuncSetAttribute(mma_gemm<1>, cudaFuncAttributeMaxDynamicSharedMemorySize, SMEM_BYTES);
    cudaFuncSetAttribute(mma_gemm<2>, cudaFuncAttributeMaxDynamicSharedMemorySize, SMEM_BYTES);
    cudaFuncSetAttribute(mma_gemm<3>, cudaFuncAttributeMaxDynamicSharedMemorySize, SMEM_BYTES);
    cudaFuncSetAttribute(mma_gemm<4>, cudaFuncAttributeMaxDynamicSharedMemorySize, SMEM_BYTES);

    // 0. all weight transposes (fp32 -> fp16 [N][K]) in one launch
    transpose_all_kernel<<<768, dim3(32, 8)>>>(qw, vw, w1, w2);

    // 1. LN1 + gate  and  text prep (fused launch)
    ln1_text_kernel<<<LN1_BLOCKS + TEXT_BLOCKS, 256>>>(visual, text,
        ln1_g, ln1_b, gate_w, gate_b);

    // 2. Q = x @ qw + qb -> fp16  (32768 x 512 x 256)
    mma_gemm<4><<<dim3(CT/128, ROWS/128, 1), 256, SMEM_BYTES>>>(
        pxt, pqwt, qb, nullptr, pq, ROWS, CT, CV, CT, CT, 0, 0, 0);

    // 3. row inv-norms of q
    qnorm_kernel<<<ROWS/8, 256>>>();

    // 4. V = text @ vw + vb -> fp32   (800 x 256 x 512)
    mma_gemm<0><<<dim3(CV/128, (BB*TT + 127)/128, 1), 256, SMEM_BYTES>>>(
        ptr, pvwt, vb, nullptr, pv, BB*TT, CV, CT, CV, CV, 0, 0, 0);

    // 5. sim = (q @ k^T) * qinv[b,m]  (4096 x 100(->128) x 512, batched)
    mma_gemm<3><<<dim3(1, NN_/128, BB), 256, SMEM_BYTES>>>(
        pq, pkn, nullptr, pqin, ps, NN_, TPAD, CT, TT, TT,
        (long)NN_*CT, (long)TPAD*CT, (long)NN_*TT);

    // 6. top-5 + softmax + gather + gate + residual + LN2
    topk_ln2_kernel<<<ROWS/8, 256>>>(lscale, alpha, ln2_g, ln2_b);

    // 7. h = gelu(y2 @ w1 + b1) -> fp16   (32768 x 1024 x 256)
    mma_gemm<1><<<dim3(4*CV/128, ROWS/128, 1), 256, SMEM_BYTES>>>(
        py2t, pw1t, b1, nullptr, ph, ROWS, 4*CV, CV, 4*CV, 4*CV, 0, 0, 0);

    // 8. out = y2 + h @ w2 + b2 -> fp32   (32768 x 256 x 1024)
    mma_gemm<2><<<dim3(CV/128, ROWS/128, 1), 256, SMEM_BYTES>>>(
        ph, pw2t, b2, py2, out, ROWS, CV, 4*CV, CV, CV, 0, 0, 0);
}

// round 11
// speedup vs baseline: 5.1895x; 1.1006x over previous
#include <cuda_runtime.h>
#include <cuda_fp16.h>
#include <math.h>
#include <cstdint>

// ---------------------------------------------------------------------------
// Problem constants
// ---------------------------------------------------------------------------
#define BB   8
#define CV   256
#define CT   512
#define TT   100
#define TPAD 128            // padded text rows for sim GEMM
#define NN_  4096           // H*W
#define ROWS (BB*NN_)       // 32768
#define TOPM 5

// ---------------------------------------------------------------------------
// Scratch (static device globals: allocation-free)
// ---------------------------------------------------------------------------
__device__ float  g_x   [ROWS * CV];        // ln1 output (fp32, residual path)
__device__ __half g_xt  [ROWS * CV];        // ln1 output (fp16, GEMM A)
__device__ float  g_gate[ROWS];             // sigmoid gate
__device__ __half g_q   [ROWS * CT];        // x@qw+qb (fp16)
__device__ float  g_qss [16 * ROWS];        // partial sum-of-squares of q rows
__device__ __half g_kn  [BB * TPAD * CT];   // l2norm(text) fp16, padded
__device__ __half g_tr  [BB * TT * CT];     // text fp16 (V GEMM A)
__device__ float  g_v   [BB * TT * CV];     // text@vw+vb (fp32)
__device__ int    g_pad [BB * TT];
__device__ float  g_sim [ROWS * TT];        // (q.k) * 1/||q||
__device__ float  g_y2  [ROWS * CV];        // ln2 output (fp32, residual)
__device__ __half g_y2t [ROWS * CV];        // ln2 output (fp16, GEMM A)
__device__ __half g_h   [ROWS * 4 * CV];    // gelu hidden (fp16)
// transposed fp16 weights ([N,K] K-major)
__device__ __half g_qwt [CT * CV];
__device__ __half g_vwt [CV * CT];
__device__ __half g_w1t [4*CV * CV];
__device__ __half g_w2t [CV * 4*CV];

// ---------------------------------------------------------------------------
// PTX helpers
// ---------------------------------------------------------------------------
__device__ __forceinline__ uint32_t smem_to_u32(const void* p) {
    uint32_t a;
    asm("{ .reg .u64 t; cvta.to.shared.u64 t, %1; cvt.u32.u64 %0, t; }"
        : "=r"(a) : "l"(p));
    return a;
}
__device__ __forceinline__ void cp16(uint32_t dst, const void* src, bool pred) {
    int sz = pred ? 16 : 0;
    asm volatile("cp.async.cg.shared.global [%0], [%1], 16, %2;\n"
        :: "r"(dst), "l"(src), "r"(sz));
}
__device__ __forceinline__ void mma16(float* c, const uint32_t* a, const uint32_t* b) {
    asm volatile(
        "mma.sync.aligned.m16n8k16.row.col.f32.f16.f16.f32 "
        "{%0,%1,%2,%3},{%4,%5,%6,%7},{%8,%9},{%0,%1,%2,%3};"
        : "+f"(c[0]), "+f"(c[1]), "+f"(c[2]), "+f"(c[3])
        : "r"(a[0]), "r"(a[1]), "r"(a[2]), "r"(a[3]), "r"(b[0]), "r"(b[1]));
}
__device__ __forceinline__ void ldsm4(uint32_t* r, uint32_t addr) {
    asm volatile("ldmatrix.sync.aligned.m8n8.x4.shared.b16 {%0,%1,%2,%3}, [%4];"
        : "=r"(r[0]), "=r"(r[1]), "=r"(r[2]), "=r"(r[3]) : "r"(addr));
}
__device__ __forceinline__ float wred(float v) {
    #pragma unroll
    for (int o = 16; o; o >>= 1) v += __shfl_xor_sync(0xffffffffu, v, o);
    return v;
}

// ---------------------------------------------------------------------------
// Fused LN1+gate (blocks [0, ROWS/8)) and text-prep (blocks [ROWS/8, +128))
// ---------------------------------------------------------------------------
#define LN1_BLOCKS (ROWS / 8)
#define TEXT_BLOCKS (BB * TPAD / 8)

__global__ void ln1_text_kernel(const float* __restrict__ vis,
                                const float* __restrict__ text,
                                const float* __restrict__ g, const float* __restrict__ b,
                                const float* __restrict__ gw, const float* __restrict__ gbp) {
    int lane = threadIdx.x & 31;
    if (blockIdx.x < LN1_BLOCKS) {
        int row = blockIdx.x * 8 + (threadIdx.x >> 5);
        const float4* vr = (const float4*)(vis + (long)row * CV);
        float4 v0 = vr[lane * 2], v1 = vr[lane * 2 + 1];
        float s = v0.x + v0.y + v0.z + v0.w + v1.x + v1.y + v1.z + v1.w;
        float mean = wred(s) * (1.f / CV);
        float d[8] = {v0.x-mean, v0.y-mean, v0.z-mean, v0.w-mean,
                      v1.x-mean, v1.y-mean, v1.z-mean, v1.w-mean};
        float sq = 0.f;
        #pragma unroll
        for (int e = 0; e < 8; e++) sq += d[e] * d[e];
        float rs = rsqrtf(wred(sq) * (1.f / CV) + 1e-5f);
        const float4* gr = (const float4*)g;  const float4* br = (const float4*)b;
        const float4* gwr = (const float4*)gw;
        float4 ga = gr[lane*2], gb4 = gr[lane*2+1], ba = br[lane*2], bb4 = br[lane*2+1];
        float4 wa = gwr[lane*2], wb = gwr[lane*2+1];
        float xv[8];
        xv[0]=d[0]*rs*ga.x+ba.x; xv[1]=d[1]*rs*ga.y+ba.y; xv[2]=d[2]*rs*ga.z+ba.z; xv[3]=d[3]*rs*ga.w+ba.w;
        xv[4]=d[4]*rs*gb4.x+bb4.x; xv[5]=d[5]*rs*gb4.y+bb4.y; xv[6]=d[6]*rs*gb4.z+bb4.z; xv[7]=d[7]*rs*gb4.w+bb4.w;
        float4* xo = (float4*)(g_x + (long)row * CV);
        xo[lane*2]   = make_float4(xv[0],xv[1],xv[2],xv[3]);
        xo[lane*2+1] = make_float4(xv[4],xv[5],xv[6],xv[7]);
        __half2* xto = (__half2*)(g_xt + (long)row * CV);
        xto[lane*4+0] = __floats2half2_rn(xv[0], xv[1]);
        xto[lane*4+1] = __floats2half2_rn(xv[2], xv[3]);
        xto[lane*4+2] = __floats2half2_rn(xv[4], xv[5]);
        xto[lane*4+3] = __floats2half2_rn(xv[6], xv[7]);
        float gp = xv[0]*wa.x+xv[1]*wa.y+xv[2]*wa.z+xv[3]*wa.w
                 + xv[4]*wb.x+xv[5]*wb.y+xv[6]*wb.z+xv[7]*wb.w;
        gp = wred(gp);
        if (lane == 0) g_gate[row] = 1.f / (1.f + expf(-(gp + gbp[0])));
    } else {
        int p = (blockIdx.x - LN1_BLOCKS) * 8 + (threadIdx.x >> 5);
        int bz = p >> 7, t = p & (TPAD - 1);
        __half2* ko = (__half2*)(g_kn + (long)p * CT);
        if (t >= TT) {
            #pragma unroll
            for (int j = 0; j < 4; j++) {
                ko[2*(lane + j*32)]     = __floats2half2_rn(0.f, 0.f);
                ko[2*(lane + j*32) + 1] = __floats2half2_rn(0.f, 0.f);
            }
            return;
        }
        const float4* tr = (const float4*)(text + ((long)bz * TT + t) * CT);
        __half2* tro = (__half2*)(g_tr + ((long)bz * TT + t) * CT);
        float4 v[4]; float sa = 0.f, ss = 0.f;
        #pragma unroll
        for (int j = 0; j < 4; j++) {
            v[j] = tr[lane + j * 32];
            sa += fabsf(v[j].x)+fabsf(v[j].y)+fabsf(v[j].z)+fabsf(v[j].w);
            ss += v[j].x*v[j].x + v[j].y*v[j].y + v[j].z*v[j].z + v[j].w*v[j].w;
        }
        sa = wred(sa); ss = wred(ss);
        if (lane == 0) g_pad[bz * TT + t] = (sa <= 1e-6f) ? 1 : 0;
        float inv = 1.f / fmaxf(sqrtf(ss), 1e-6f);
        #pragma unroll
        for (int j = 0; j < 4; j++) {
            ko[2*(lane + j*32)]     = __floats2half2_rn(v[j].x*inv, v[j].y*inv);
            ko[2*(lane + j*32) + 1] = __floats2half2_rn(v[j].z*inv, v[j].w*inv);
            tro[2*(lane + j*32)]     = __floats2half2_rn(v[j].x, v[j].y);
            tro[2*(lane + j*32) + 1] = __floats2half2_rn(v[j].z, v[j].w);
        }
    }
}

// ---------------------------------------------------------------------------
// All 4 weight transposes in ONE launch. dst[n*K+k] = (half)src[k*N+n].
// ---------------------------------------------------------------------------
__device__ __forceinline__ void tr_tile(const float* __restrict__ src,
                                        __half* __restrict__ dst,
                                        int Kd, int Nd, int bx, int by,
                                        float (*t)[33]) {
    int k0 = by * 32, n0 = bx * 32;
    int x = threadIdx.x, y = threadIdx.y;
    #pragma unroll
    for (int i = 0; i < 32; i += 8)
        t[y + i][x] = src[(long)(k0 + y + i) * Nd + n0 + x];
    __syncthreads();
    #pragma unroll
    for (int i = 0; i < 32; i += 8)
        dst[(long)(n0 + y + i) * Kd + k0 + x] = __float2half_rn(t[x][y + i]);
}

__global__ void transpose_all_kernel(const float* __restrict__ qw, const float* __restrict__ vw,
                                     const float* __restrict__ w1, const float* __restrict__ w2) {
    __shared__ float t[32][33];
    int id = blockIdx.x;
    if (id < 128)       tr_tile(qw, g_qwt, CV, CT, id & 15, id >> 4, t);
    else if (id < 256)  { id -= 128; tr_tile(vw, g_vwt, CT, CV, id & 7, id >> 3, t); }
    else if (id < 512)  { id -= 256; tr_tile(w1, g_w1t, CV, 4*CV, id & 31, id >> 5, t); }
    else                { id -= 512; tr_tile(w2, g_w2t, 4*CV, CV, id & 7, id >> 3, t); }
}

// ---------------------------------------------------------------------------
// fp16 mma.sync GEMM: C = A[M,K] · Bt[N,K]^T (+bias/epilogue)
//   EPI 0: +bias -> fp32                 1: +bias, GELU -> fp16
//   EPI 2: +bias +residual -> fp32 (out) 3: row-scale by rsqrt(sum g_qss) -> fp32
//   EPI 4: +bias -> fp16, write qss partials
// CTA 128x128, BK=64, 8 warps (2x4), warp 64x32.
// 3-stage cp.async, ONE __syncthreads per chunk.
// ---------------------------------------------------------------------------
#define SPITCH 72                         // halfs per smem row (144 B)
#define TILE_H (128 * SPITCH)
#define STAGE_H (2 * TILE_H)
#define NSTAGE 3
#define SMEM_BYTES (NSTAGE * STAGE_H * 2) // 110592 bytes

template<int EPI>
__global__ __launch_bounds__(256, 2) void mma_gemm(
    const __half* __restrict__ A, const __half* __restrict__ Bt,
    const float* __restrict__ bias, const float* __restrict__ R,
    void* __restrict__ Cv, int M, int N, int K,
    int ldc, int n_store, long sA, long sB, long sC)
{
    extern __shared__ __half smem[];
    uint32_t sbase = smem_to_u32(smem);

    A  += (long)blockIdx.z * sA;
    Bt += (long)blockIdx.z * sB;
    float*  Cf = (float*)Cv  + (long)blockIdx.z * sC;
    __half* Ch = (__half*)Cv + (long)blockIdx.z * sC;
    const float* Rp = (EPI == 2) ? (R + (long)blockIdx.z * sC)
                    : (EPI == 3) ? (R + (long)blockIdx.z * M) : R;

    int tid = threadIdx.x, wid = tid >> 5, lane = tid & 31;
    int wm = wid & 1, wn = wid >> 1;
    int lr = lane >> 2, lc = lane & 3;
    int m0 = blockIdx.y * 128, n0 = blockIdx.x * 128;

    int sel = lane >> 3, l8 = lane & 7;
    uint32_t aOff = (uint32_t)(((wm * 64 + (sel & 1) * 8 + l8) * SPITCH + (sel >> 1) * 8) * 2);
    uint32_t bOff = (uint32_t)(((wn * 32 + (sel >> 1) * 8 + l8) * SPITCH + (sel & 1) * 8) * 2);

    float acc[4][4][4];
    #pragma unroll
    for (int i = 0; i < 4; i++)
        #pragma unroll
        for (int j = 0; j < 4; j++)
            #pragma unroll
            for (int e = 0; e < 4; e++) acc[i][j][e] = 0.f;

    int nc = K >> 6;   // BK = 64

    auto load_chunk = [&](int buf, int kc) {
        uint32_t a_s = sbase + (uint32_t)(buf * STAGE_H) * 2u;
        uint32_t b_s = a_s + (uint32_t)TILE_H * 2u;
        long koff = (long)kc * 64;
        #pragma unroll
        for (int i = 0; i < 4; i++) {
            int p = tid + 256 * i;                 // 0..1023
            int r = p >> 3, k8 = (p & 7) * 8;
            uint32_t off = (uint32_t)(r * SPITCH + k8) * 2u;
            cp16(a_s + off, A + (long)(m0 + r) * K + koff + k8, (m0 + r) < M);
        }
        #pragma unroll
        for (int i = 0; i < 4; i++) {
            int p = tid + 256 * i;
            int r = p >> 3, k8 = (p & 7) * 8;
            uint32_t off = (uint32_t)(r * SPITCH + k8) * 2u;
            cp16(b_s + off, Bt + (long)(n0 + r) * K + koff + k8, (n0 + r) < N);
        }
        asm volatile("cp.async.commit_group;\n" ::: "memory");
    };

    // prologue: 2 chunks in flight
    load_chunk(0, 0);
    if (nc > 1) load_chunk(1, 1);
    else        asm volatile("cp.async.commit_group;\n" ::: "memory");

    for (int c = 0; c < nc; c++) {
        int buf = c % NSTAGE;
        asm volatile("cp.async.wait_group 1;\n" ::: "memory");
        __syncthreads();   // chunk c resident; all warps done with chunk c-1

        if (c + 2 < nc) load_chunk((c + 2) % NSTAGE, c + 2);
        else asm volatile("cp.async.commit_group;\n" ::: "memory");

        uint32_t aBase = sbase + (uint32_t)(buf * STAGE_H) * 2u + aOff;
        uint32_t bBase = sbase + (uint32_t)(buf * STAGE_H + TILE_H) * 2u + bOff;

        #pragma unroll
        for (int ks = 0; ks < 4; ks++) {
            uint32_t kbyte = (uint32_t)(ks * 16 * 2);
            uint32_t af[4][4], bf[2][4];
            #pragma unroll
            for (int mi = 0; mi < 4; mi++)
                ldsm4(af[mi], aBase + (uint32_t)(mi * 16 * SPITCH * 2) + kbyte);
            #pragma unroll
            for (int np = 0; np < 2; np++)
                ldsm4(bf[np], bBase + (uint32_t)(np * 16 * SPITCH * 2) + kbyte);
            #pragma unroll
            for (int mi = 0; mi < 4; mi++)
                #pragma unroll
                for (int ni = 0; ni < 4; ni++)
                    mma16(acc[mi][ni], af[mi], &bf[ni >> 1][(ni & 1) * 2]);
        }
    }

    // ---- EPI 3: stage 16 qss partials per row into smem scratch ----
    float* qs = (float*)smem;
    if (EPI == 3) {
        __syncthreads();
        #pragma unroll
        for (int i = 0; i < 8; i++) {
            int idx = tid + 256 * i;            // 0..2047
            int p = idx >> 7, row = idx & 127;
            qs[row * 17 + p] = Rp[(long)p * ROWS + m0 + row];
        }
        __syncthreads();
    }

    // ---- epilogue ----
    #pragma unroll
    for (int mi = 0; mi < 4; mi++) {
        #pragma unroll
        for (int half_ = 0; half_ < 2; half_++) {
            int m = m0 + wm * 64 + mi * 16 + lr + half_ * 8;
            if (m >= M) continue;
            float rscale = 0.f;
            if (EPI == 3) {
                float ss = 0.f;
                #pragma unroll
                for (int i = 0; i < 16; i++) ss += qs[(m - m0) * 17 + i];
                rscale = 1.f / fmaxf(sqrtf(ss), 1e-6f);
            }
            float ps = 0.f;
            #pragma unroll
            for (int ni = 0; ni < 4; ni++) {
                int n = n0 + wn * 32 + ni * 8 + 2 * lc;
                if (EPI == 1 || EPI == 4) {
                    float x0 = acc[mi][ni][half_ * 2 + 0] + bias[n];
                    float x1 = acc[mi][ni][half_ * 2 + 1] + bias[n + 1];
                    if (EPI == 4) ps += x0 * x0 + x1 * x1;
                    if (EPI == 1) {
                        x0 = 0.5f * x0 * (1.f + erff(x0 * 0.70710678118654752f));
                        x1 = 0.5f * x1 * (1.f + erff(x1 * 0.70710678118654752f));
                    }
                    *(__half2*)(Ch + (long)m * ldc + n) = __floats2half2_rn(x0, x1);
                } else {
                    #pragma unroll
                    for (int e = 0; e < 2; e++) {
                        int ne = n + e;
                        if (ne >= n_store) continue;
                        float x = acc[mi][ni][half_ * 2 + e];
                        if (EPI != 3 && bias) x += bias[ne];
                        if (EPI == 2) x += Rp[(long)m * ldc + ne];
                        if (EPI == 3) x *= rscale;
                        Cf[(long)m * ldc + ne] = x;
                    }
                }
            }
            if (EPI == 4) {
                // reduce over the quad (lanes sharing this row), deterministic tree
                ps += __shfl_xor_sync(0xffffffffu, ps, 1);
                ps += __shfl_xor_sync(0xffffffffu, ps, 2);
                if (lc == 0)
                    g_qss[(long)(blockIdx.x * 4 + wn) * ROWS + m] = ps;
            }
        }
    }
}

// ---------------------------------------------------------------------------
// top-5 + softmax + gather + gate + residual + fused LN2 (one warp per pixel)
// ---------------------------------------------------------------------------
__global__ void topk_ln2_kernel(const float* __restrict__ logit_scale,
                                const float* __restrict__ alpha_p,
                                const float* __restrict__ g2,
                                const float* __restrict__ b2) {
    int warp = (blockIdx.x * blockDim.x + threadIdx.x) >> 5;
    int lane = threadIdx.x & 31;
    int b = warp >> 12;

    float ls = logit_scale[0];
    float scale = expf(fminf(fmaxf(ls, -2.f), 2.f)) * rsqrtf((float)CT);
    float alpha = alpha_p[0];

    const float* srow = g_sim + (long)warp * TT;
    float vals[4]; int idxs[4];
    #pragma unroll
    for (int i = 0; i < 4; i++) {
        int t = lane + 32 * i;
        if (t < TT) { vals[i] = srow[t] * scale; idxs[i] = t; }
        else        { vals[i] = -INFINITY;       idxs[i] = 0x7fffffff; }
    }

    float wv[TOPM]; int wi[TOPM];
    #pragma unroll
    for (int m = 0; m < TOPM; m++) {
        float bv = vals[0]; int bi = idxs[0];
        #pragma unroll
        for (int i = 1; i < 4; i++)
            if (vals[i] > bv || (vals[i] == bv && idxs[i] < bi)) { bv = vals[i]; bi = idxs[i]; }
        float rv = bv; int ri = bi;
        #pragma unroll
        for (int off = 16; off; off >>= 1) {
            float ov = __shfl_xor_sync(0xffffffffu, rv, off);
            int   oi = __shfl_xor_sync(0xffffffffu, ri, off);
            if (ov > rv || (ov == rv && oi < ri)) { rv = ov; ri = oi; }
        }
        wv[m] = rv; wi[m] = ri;
        if ((ri & 31) == lane) {
            int s = ri >> 5;
            vals[s] = -INFINITY; idxs[s] = 0x7fffffff;
        }
    }

    float mx = -INFINITY;
    #pragma unroll
    for (int m = 0; m < TOPM; m++) {
        if (g_pad[b * TT + wi[m]]) wv[m] = -INFINITY;
        mx = fmaxf(mx, wv[m]);
    }
    float e[TOPM]; float se = 0.f;
    #pragma unroll
    for (int m = 0; m < TOPM; m++) {
        e[m] = (wv[m] == -INFINITY) ? 0.f : expf(wv[m] - mx);
        se += e[m];
    }
    float inv = 1.f / se;
    float ag = alpha * g_gate[warp];

    long rowoff = (long)warp * CV;
    float yv[8];
    #pragma unroll
    for (int j = 0; j < 8; j++) {
        int c = lane + 32 * j;
        float acc = 0.f;
        #pragma unroll
        for (int m = 0; m < TOPM; m++)
            acc = fmaf(e[m] * inv, g_v[(long)(b * TT + wi[m]) * CV + c], acc);
        yv[j] = g_x[rowoff + c] + ag * acc;
    }
    // fused LayerNorm2
    float s = 0.f;
    #pragma unroll
    for (int j = 0; j < 8; j++) s += yv[j];
    float mean = wred(s) * (1.f / CV);
    float sq = 0.f;
    #pragma unroll
    for (int j = 0; j < 8; j++) { float d = yv[j] - mean; sq += d * d; }
    float rs = rsqrtf(wred(sq) * (1.f / CV) + 1e-5f);
    #pragma unroll
    for (int j = 0; j < 8; j++) {
        int c = lane + 32 * j;
        float y2 = (yv[j] - mean) * rs * g2[c] + b2[c];
        g_y2 [rowoff + c] = y2;
        g_y2t[rowoff + c] = __float2half_rn(y2);
    }
}

// ---------------------------------------------------------------------------
// Launch
// ---------------------------------------------------------------------------
static void* symaddr(const void* sym) {
    void* p = nullptr;
    cudaGetSymbolAddress(&p, sym);
    return p;
}

extern "C" void kernel_launch(void* const* d_in, const int* in_sizes, int n_in,
                              void* d_out, int out_size) {
    const float* visual = (const float*)d_in[0];
    const float* text   = (const float*)d_in[1];
    const float* ln1_g  = (const float*)d_in[2];
    const float* ln1_b  = (const float*)d_in[3];
    const float* qw     = (const float*)d_in[4];
    const float* qb     = (const float*)d_in[5];
    const float* vw     = (const float*)d_in[6];
    const float* vb     = (const float*)d_in[7];
    const float* gate_w = (const float*)d_in[8];
    const float* gate_b = (const float*)d_in[9];
    const float* lscale = (const float*)d_in[10];
    const float* alpha  = (const float*)d_in[11];
    const float* ln2_g  = (const float*)d_in[12];
    const float* ln2_b  = (const float*)d_in[13];
    const float* w1     = (const float*)d_in[14];
    const float* b1     = (const float*)d_in[15];
    const float* w2     = (const float*)d_in[16];
    const float* b2     = (const float*)d_in[17];
    float* out = (float*)d_out;

    __half* pxt  = (__half*)symaddr(g_xt);
    __half* pq   = (__half*)symaddr(g_q);
    float*  pqss = (float*) symaddr(g_qss);
    __half* pkn  = (__half*)symaddr(g_kn);
    __half* ptr  = (__half*)symaddr(g_tr);
    float*  pv   = (float*) symaddr(g_v);
    float*  ps   = (float*) symaddr(g_sim);
    float*  py2  = (float*) symaddr(g_y2);
    __half* py2t = (__half*)symaddr(g_y2t);
    __half* ph   = (__half*)symaddr(g_h);
    __half* pqwt = (__half*)symaddr(g_qwt);
    __half* pvwt = (__half*)symaddr(g_vwt);
    __half* pw1t = (__half*)symaddr(g_w1t);
    __half* pw2t = (__half*)symaddr(g_w2t);

    cudaFuncSetAttribute(mma_gemm<0>, cudaFuncAttributeMaxDynamicSharedMemorySize, SMEM_BYTES);
    cudaFuncSetAttribute(mma_gemm<1>, cudaFuncAttributeMaxDynamicSharedMemorySize, SMEM_BYTES);
    cudaFuncSetAttribute(mma_gemm<2>, cudaFuncAttributeMaxDynamicSharedMemorySize, SMEM_BYTES);
    cudaFuncSetAttribute(mma_gemm<3>, cudaFuncAttributeMaxDynamicSharedMemorySize, SMEM_BYTES);
    cudaFuncSetAttribute(mma_gemm<4>, cudaFuncAttributeMaxDynamicSharedMemorySize, SMEM_BYTES);

    // 0. all weight transposes (fp32 -> fp16 [N][K]) in one launch
    transpose_all_kernel<<<768, dim3(32, 8)>>>(qw, vw, w1, w2);

    // 1. LN1 + gate  and  text prep (fused launch)
    ln1_text_kernel<<<LN1_BLOCKS + TEXT_BLOCKS, 256>>>(visual, text,
        ln1_g, ln1_b, gate_w, gate_b);

    // 2. Q = x @ qw + qb -> fp16, plus qss partials  (32768 x 512 x 256)
    mma_gemm<4><<<dim3(CT/128, ROWS/128, 1), 256, SMEM_BYTES>>>(
        pxt, pqwt, qb, nullptr, pq, ROWS, CT, CV, CT, CT, 0, 0, 0);

    // 3. V = text @ vw + vb -> fp32   (800 x 256 x 512)
    mma_gemm<0><<<dim3(CV/128, (BB*TT + 127)/128, 1), 256, SMEM_BYTES>>>(
        ptr, pvwt, vb, nullptr, pv, BB*TT, CV, CT, CV, CV, 0, 0, 0);

    // 4. sim = (q @ k^T) * rsqrt(sum qss)  (4096 x 100(->128) x 512, batched)
    mma_gemm<3><<<dim3(1, NN_/128, BB), 256, SMEM_BYTES>>>(
        pq, pkn, nullptr, pqss, ps, NN_, TPAD, CT, TT, TT,
        (long)NN_*CT, (long)TPAD*CT, (long)NN_*TT);

    // 5. top-5 + softmax + gather + gate + residual + LN2
    topk_ln2_kernel<<<ROWS/8, 256>>>(lscale, alpha, ln2_g, ln2_b);

    // 6. h = gelu(y2 @ w1 + b1) -> fp16   (32768 x 1024 x 256)
    mma_gemm<1><<<dim3(4*CV/128, ROWS/128, 1), 256, SMEM_BYTES>>>(
        py2t, pw1t, b1, nullptr, ph, ROWS, 4*CV, CV, 4*CV, 4*CV, 0, 0, 0);

    // 7. out = y2 + h @ w2 + b2 -> fp32   (32768 x 256 x 1024)
    mma_gemm<2><<<dim3(CV/128, ROWS/128, 1), 256, SMEM_BYTES>>>(
        ph, pw2t, b2, py2, out, ROWS, CV, 4*CV, CV, CV, 0, 0, 0);
}

// round 12
// speedup vs baseline: 5.3994x; 1.0404x over previous
#include <cuda_runtime.h>
#include <cuda_fp16.h>
#include <math.h>
#include <cstdint>

// ---------------------------------------------------------------------------
// Problem constants
// ---------------------------------------------------------------------------
#define BB   8
#define CV   256
#define CT   512
#define TT   100
#define TPAD 128            // padded text rows for sim GEMM
#define NN_  4096           // H*W
#define ROWS (BB*NN_)       // 32768
#define TOPM 5

// ---------------------------------------------------------------------------
// Scratch (static device globals: allocation-free)
// ---------------------------------------------------------------------------
__device__ float  g_x   [ROWS * CV];        // ln1 output (fp32, residual path)
__device__ __half g_xt  [ROWS * CV];        // ln1 output (fp16, GEMM A)
__device__ float  g_gate[ROWS];             // sigmoid gate
__device__ __half g_q   [ROWS * CT];        // x@qw+qb (fp16)
__device__ float  g_qss [16 * ROWS];        // partial sum-of-squares of q rows
__device__ __half g_kn  [BB * TPAD * CT];   // l2norm(text) fp16, padded
__device__ __half g_tr  [BB * TT * CT];     // text fp16 (V GEMM A)
__device__ float  g_v   [BB * TT * CV];     // text@vw+vb (fp32)
__device__ int    g_pad [BB * TT];
__device__ float  g_sim [ROWS * TT];        // (q.k) * 1/||q||
__device__ float  g_y2  [ROWS * CV];        // ln2 output (fp32, residual)
__device__ __half g_y2t [ROWS * CV];        // ln2 output (fp16, GEMM A)
__device__ __half g_h   [ROWS * 4 * CV];    // gelu hidden (fp16)
// transposed fp16 weights ([N,K] K-major)
__device__ __half g_qwt [CT * CV];
__device__ __half g_vwt [CV * CT];
__device__ __half g_w1t [4*CV * CV];
__device__ __half g_w2t [CV * 4*CV];

// ---------------------------------------------------------------------------
// PTX helpers
// ---------------------------------------------------------------------------
__device__ __forceinline__ uint32_t smem_to_u32(const void* p) {
    uint32_t a;
    asm("{ .reg .u64 t; cvta.to.shared.u64 t, %1; cvt.u32.u64 %0, t; }"
        : "=r"(a) : "l"(p));
    return a;
}
__device__ __forceinline__ void cp16(uint32_t dst, const void* src, bool pred) {
    int sz = pred ? 16 : 0;
    asm volatile("cp.async.cg.shared.global [%0], [%1], 16, %2;\n"
        :: "r"(dst), "l"(src), "r"(sz));
}
__device__ __forceinline__ void mma16(float* c, const uint32_t* a, const uint32_t* b) {
    asm volatile(
        "mma.sync.aligned.m16n8k16.row.col.f32.f16.f16.f32 "
        "{%0,%1,%2,%3},{%4,%5,%6,%7},{%8,%9},{%0,%1,%2,%3};"
        : "+f"(c[0]), "+f"(c[1]), "+f"(c[2]), "+f"(c[3])
        : "r"(a[0]), "r"(a[1]), "r"(a[2]), "r"(a[3]), "r"(b[0]), "r"(b[1]));
}
__device__ __forceinline__ void ldsm4(uint32_t* r, uint32_t addr) {
    asm volatile("ldmatrix.sync.aligned.m8n8.x4.shared.b16 {%0,%1,%2,%3}, [%4];"
        : "=r"(r[0]), "=r"(r[1]), "=r"(r[2]), "=r"(r[3]) : "r"(addr));
}
__device__ __forceinline__ float wred(float v) {
    #pragma unroll
    for (int o = 16; o; o >>= 1) v += __shfl_xor_sync(0xffffffffu, v, o);
    return v;
}

// ---------------------------------------------------------------------------
// Prep kernel: blocks [0,768) weight transposes, [768, 768+4096) LN1+gate,
// then 128 text-prep blocks. 256 threads each.
// ---------------------------------------------------------------------------
#define TR_BLOCKS 768
#define LN1_BLOCKS (ROWS / 8)
#define TEXT_BLOCKS (BB * TPAD / 8)

__device__ __forceinline__ void tr_tile(const float* __restrict__ src,
                                        __half* __restrict__ dst,
                                        int Kd, int Nd, int bx, int by,
                                        float (*t)[33], int x, int y) {
    int k0 = by * 32, n0 = bx * 32;
    #pragma unroll
    for (int i = 0; i < 32; i += 8)
        t[y + i][x] = src[(long)(k0 + y + i) * Nd + n0 + x];
    __syncthreads();
    #pragma unroll
    for (int i = 0; i < 32; i += 8)
        dst[(long)(n0 + y + i) * Kd + k0 + x] = __float2half_rn(t[x][y + i]);
}

__global__ void prep_kernel(const float* __restrict__ vis,
                            const float* __restrict__ text,
                            const float* __restrict__ qw, const float* __restrict__ vw,
                            const float* __restrict__ w1, const float* __restrict__ w2,
                            const float* __restrict__ g, const float* __restrict__ b,
                            const float* __restrict__ gw, const float* __restrict__ gbp) {
    __shared__ float t[32][33];
    int lane = threadIdx.x & 31;
    if (blockIdx.x < TR_BLOCKS) {
        int id = blockIdx.x;
        int x = threadIdx.x & 31, y = threadIdx.x >> 5;
        if (id < 128)       tr_tile(qw, g_qwt, CV, CT, id & 15, id >> 4, t, x, y);
        else if (id < 256)  { id -= 128; tr_tile(vw, g_vwt, CT, CV, id & 7, id >> 3, t, x, y); }
        else if (id < 512)  { id -= 256; tr_tile(w1, g_w1t, CV, 4*CV, id & 31, id >> 5, t, x, y); }
        else                { id -= 512; tr_tile(w2, g_w2t, 4*CV, CV, id & 7, id >> 3, t, x, y); }
    } else if (blockIdx.x < TR_BLOCKS + LN1_BLOCKS) {
        int row = (blockIdx.x - TR_BLOCKS) * 8 + (threadIdx.x >> 5);
        const float4* vr = (const float4*)(vis + (long)row * CV);
        float4 v0 = vr[lane * 2], v1 = vr[lane * 2 + 1];
        float s = v0.x + v0.y + v0.z + v0.w + v1.x + v1.y + v1.z + v1.w;
        float mean = wred(s) * (1.f / CV);
        float d[8] = {v0.x-mean, v0.y-mean, v0.z-mean, v0.w-mean,
                      v1.x-mean, v1.y-mean, v1.z-mean, v1.w-mean};
        float sq = 0.f;
        #pragma unroll
        for (int e = 0; e < 8; e++) sq += d[e] * d[e];
        float rs = rsqrtf(wred(sq) * (1.f / CV) + 1e-5f);
        const float4* gr = (const float4*)g;  const float4* br = (const float4*)b;
        const float4* gwr = (const float4*)gw;
        float4 ga = gr[lane*2], gb4 = gr[lane*2+1], ba = br[lane*2], bb4 = br[lane*2+1];
        float4 wa = gwr[lane*2], wb = gwr[lane*2+1];
        float xv[8];
        xv[0]=d[0]*rs*ga.x+ba.x; xv[1]=d[1]*rs*ga.y+ba.y; xv[2]=d[2]*rs*ga.z+ba.z; xv[3]=d[3]*rs*ga.w+ba.w;
        xv[4]=d[4]*rs*gb4.x+bb4.x; xv[5]=d[5]*rs*gb4.y+bb4.y; xv[6]=d[6]*rs*gb4.z+bb4.z; xv[7]=d[7]*rs*gb4.w+bb4.w;
        float4* xo = (float4*)(g_x + (long)row * CV);
        xo[lane*2]   = make_float4(xv[0],xv[1],xv[2],xv[3]);
        xo[lane*2+1] = make_float4(xv[4],xv[5],xv[6],xv[7]);
        __half2* xto = (__half2*)(g_xt + (long)row * CV);
        xto[lane*4+0] = __floats2half2_rn(xv[0], xv[1]);
        xto[lane*4+1] = __floats2half2_rn(xv[2], xv[3]);
        xto[lane*4+2] = __floats2half2_rn(xv[4], xv[5]);
        xto[lane*4+3] = __floats2half2_rn(xv[6], xv[7]);
        float gp = xv[0]*wa.x+xv[1]*wa.y+xv[2]*wa.z+xv[3]*wa.w
                 + xv[4]*wb.x+xv[5]*wb.y+xv[6]*wb.z+xv[7]*wb.w;
        gp = wred(gp);
        if (lane == 0) g_gate[row] = 1.f / (1.f + expf(-(gp + gbp[0])));
    } else {
        int p = (blockIdx.x - TR_BLOCKS - LN1_BLOCKS) * 8 + (threadIdx.x >> 5);
        int bz = p >> 7, tt = p & (TPAD - 1);
        __half2* ko = (__half2*)(g_kn + (long)p * CT);
        if (tt >= TT) {
            #pragma unroll
            for (int j = 0; j < 4; j++) {
                ko[2*(lane + j*32)]     = __floats2half2_rn(0.f, 0.f);
                ko[2*(lane + j*32) + 1] = __floats2half2_rn(0.f, 0.f);
            }
            return;
        }
        const float4* tr = (const float4*)(text + ((long)bz * TT + tt) * CT);
        __half2* tro = (__half2*)(g_tr + ((long)bz * TT + tt) * CT);
        float4 v[4]; float sa = 0.f, ss = 0.f;
        #pragma unroll
        for (int j = 0; j < 4; j++) {
            v[j] = tr[lane + j * 32];
            sa += fabsf(v[j].x)+fabsf(v[j].y)+fabsf(v[j].z)+fabsf(v[j].w);
            ss += v[j].x*v[j].x + v[j].y*v[j].y + v[j].z*v[j].z + v[j].w*v[j].w;
        }
        sa = wred(sa); ss = wred(ss);
        if (lane == 0) g_pad[bz * TT + tt] = (sa <= 1e-6f) ? 1 : 0;
        float inv = 1.f / fmaxf(sqrtf(ss), 1e-6f);
        #pragma unroll
        for (int j = 0; j < 4; j++) {
            ko[2*(lane + j*32)]     = __floats2half2_rn(v[j].x*inv, v[j].y*inv);
            ko[2*(lane + j*32) + 1] = __floats2half2_rn(v[j].z*inv, v[j].w*inv);
            tro[2*(lane + j*32)]     = __floats2half2_rn(v[j].x, v[j].y);
            tro[2*(lane + j*32) + 1] = __floats2half2_rn(v[j].z, v[j].w);
        }
    }
}

// ---------------------------------------------------------------------------
// Shared GEMM machinery. CTA 128x128, BK=64, 8 warps (2x4), warp 64x32.
// 3-stage cp.async, one __syncthreads per chunk.
// ---------------------------------------------------------------------------
#define SPITCH 72                         // halfs per smem row (144 B)
#define TILE_H (128 * SPITCH)
#define STAGE_H (2 * TILE_H)
#define NSTAGE 3
#define SMEM_BYTES (NSTAGE * STAGE_H * 2) // 110592 bytes

struct FragCtx {
    uint32_t sbase, aOff, bOff;
    int tid, wm, wn, lr, lc;
};

__device__ __forceinline__ void gemm_mainloop(
    const __half* __restrict__ A, const __half* __restrict__ Bt,
    int M, int N, int K, int m0, int n0, const FragCtx& fc,
    float acc[4][4][4])
{
    int tid = fc.tid;
    int nc = K >> 6;

    auto load_chunk = [&](int buf, int kc) {
        uint32_t a_s = fc.sbase + (uint32_t)(buf * STAGE_H) * 2u;
        uint32_t b_s = a_s + (uint32_t)TILE_H * 2u;
        long koff = (long)kc * 64;
        #pragma unroll
        for (int i = 0; i < 4; i++) {
            int p = tid + 256 * i;
            int r = p >> 3, k8 = (p & 7) * 8;
            uint32_t off = (uint32_t)(r * SPITCH + k8) * 2u;
            cp16(a_s + off, A + (long)(m0 + r) * K + koff + k8, (m0 + r) < M);
        }
        #pragma unroll
        for (int i = 0; i < 4; i++) {
            int p = tid + 256 * i;
            int r = p >> 3, k8 = (p & 7) * 8;
            uint32_t off = (uint32_t)(r * SPITCH + k8) * 2u;
            cp16(b_s + off, Bt + (long)(n0 + r) * K + koff + k8, (n0 + r) < N);
        }
        asm volatile("cp.async.commit_group;\n" ::: "memory");
    };

    load_chunk(0, 0);
    if (nc > 1) load_chunk(1, 1);
    else        asm volatile("cp.async.commit_group;\n" ::: "memory");

    for (int c = 0; c < nc; c++) {
        int buf = c % NSTAGE;
        asm volatile("cp.async.wait_group 1;\n" ::: "memory");
        __syncthreads();

        if (c + 2 < nc) load_chunk((c + 2) % NSTAGE, c + 2);
        else asm volatile("cp.async.commit_group;\n" ::: "memory");

        uint32_t aBase = fc.sbase + (uint32_t)(buf * STAGE_H) * 2u + fc.aOff;
        uint32_t bBase = fc.sbase + (uint32_t)(buf * STAGE_H + TILE_H) * 2u + fc.bOff;

        #pragma unroll
        for (int ks = 0; ks < 4; ks++) {
            uint32_t kbyte = (uint32_t)(ks * 16 * 2);
            uint32_t af[4][4], bf[2][4];
            #pragma unroll
            for (int mi = 0; mi < 4; mi++)
                ldsm4(af[mi], aBase + (uint32_t)(mi * 16 * SPITCH * 2) + kbyte);
            #pragma unroll
            for (int np = 0; np < 2; np++)
                ldsm4(bf[np], bBase + (uint32_t)(np * 16 * SPITCH * 2) + kbyte);
            #pragma unroll
            for (int mi = 0; mi < 4; mi++)
                #pragma unroll
                for (int ni = 0; ni < 4; ni++)
                    mma16(acc[mi][ni], af[mi], &bf[ni >> 1][(ni & 1) * 2]);
        }
    }
}

__device__ __forceinline__ FragCtx make_ctx(uint32_t sbase) {
    FragCtx fc;
    int tid = threadIdx.x, wid = tid >> 5, lane = tid & 31;
    fc.tid = tid;
    fc.wm = wid & 1; fc.wn = wid >> 1;
    fc.lr = lane >> 2; fc.lc = lane & 3;
    int sel = lane >> 3, l8 = lane & 7;
    fc.sbase = sbase;
    fc.aOff = (uint32_t)(((fc.wm * 64 + (sel & 1) * 8 + l8) * SPITCH + (sel >> 1) * 8) * 2);
    fc.bOff = (uint32_t)(((fc.wn * 32 + (sel >> 1) * 8 + l8) * SPITCH + (sel & 1) * 8) * 2);
    return fc;
}

// ---------------------------------------------------------------------------
// Fused Q + V GEMM.
//   blocks [0,1024):  Q = g_xt @ g_qwt^T + qb  -> g_q (fp16) + qss partials
//                     grid decode: bx = id&3 (N), by = id>>2 (M)
//   blocks [1024,1038): V = g_tr @ g_vwt^T + vb -> g_v (fp32)
//                     id2 = id-1024: bx = id2&1, by = id2>>1   (M=800)
// ---------------------------------------------------------------------------
__global__ __launch_bounds__(256, 2) void qv_gemm(
    const float* __restrict__ qb, const float* __restrict__ vb)
{
    extern __shared__ __half smem[];
    FragCtx fc = make_ctx(smem_to_u32(smem));
    float acc[4][4][4];
    #pragma unroll
    for (int i = 0; i < 4; i++)
        #pragma unroll
        for (int j = 0; j < 4; j++)
            #pragma unroll
            for (int e = 0; e < 4; e++) acc[i][j][e] = 0.f;

    if (blockIdx.x < 1024) {
        int bx = blockIdx.x & 3, by = blockIdx.x >> 2;
        int m0 = by * 128, n0 = bx * 128;
        gemm_mainloop(g_xt, g_qwt, ROWS, CT, CV, m0, n0, fc, acc);
        // epilogue: +bias -> fp16 g_q, qss partials
        #pragma unroll
        for (int mi = 0; mi < 4; mi++) {
            #pragma unroll
            for (int half_ = 0; half_ < 2; half_++) {
                int m = m0 + fc.wm * 64 + mi * 16 + fc.lr + half_ * 8;
                float ps = 0.f;
                #pragma unroll
                for (int ni = 0; ni < 4; ni++) {
                    int n = n0 + fc.wn * 32 + ni * 8 + 2 * fc.lc;
                    float x0 = acc[mi][ni][half_ * 2 + 0] + qb[n];
                    float x1 = acc[mi][ni][half_ * 2 + 1] + qb[n + 1];
                    ps += x0 * x0 + x1 * x1;
                    *(__half2*)(g_q + (long)m * CT + n) = __floats2half2_rn(x0, x1);
                }
                ps += __shfl_xor_sync(0xffffffffu, ps, 1);
                ps += __shfl_xor_sync(0xffffffffu, ps, 2);
                if (fc.lc == 0)
                    g_qss[(long)(bx * 4 + fc.wn) * ROWS + m] = ps;
            }
        }
    } else {
        int id2 = blockIdx.x - 1024;
        int bx = id2 & 1, by = id2 >> 1;
        int m0 = by * 128, n0 = bx * 128;
        gemm_mainloop(g_tr, g_vwt, BB * TT, CV, CT, m0, n0, fc, acc);
        // epilogue: +bias -> fp32 g_v
        #pragma unroll
        for (int mi = 0; mi < 4; mi++) {
            #pragma unroll
            for (int half_ = 0; half_ < 2; half_++) {
                int m = m0 + fc.wm * 64 + mi * 16 + fc.lr + half_ * 8;
                if (m >= BB * TT) continue;
                #pragma unroll
                for (int ni = 0; ni < 4; ni++) {
                    int n = n0 + fc.wn * 32 + ni * 8 + 2 * fc.lc;
                    g_v[(long)m * CV + n]     = acc[mi][ni][half_ * 2 + 0] + vb[n];
                    g_v[(long)m * CV + n + 1] = acc[mi][ni][half_ * 2 + 1] + vb[n + 1];
                }
            }
        }
    }
}

// ---------------------------------------------------------------------------
// mma_gemm template for sim (EPI 3), MLP1 (EPI 1), MLP2 (EPI 2)
// ---------------------------------------------------------------------------
template<int EPI>
__global__ __launch_bounds__(256, 2) void mma_gemm(
    const __half* __restrict__ A, const __half* __restrict__ Bt,
    const float* __restrict__ bias, const float* __restrict__ R,
    void* __restrict__ Cv, int M, int N, int K,
    int ldc, int n_store, long sA, long sB, long sC)
{
    extern __shared__ __half smem[];
    FragCtx fc = make_ctx(smem_to_u32(smem));

    A  += (long)blockIdx.z * sA;
    Bt += (long)blockIdx.z * sB;
    float*  Cf = (float*)Cv  + (long)blockIdx.z * sC;
    __half* Ch = (__half*)Cv + (long)blockIdx.z * sC;
    const float* Rp = (EPI == 2) ? (R + (long)blockIdx.z * sC)
                    : (EPI == 3) ? (R + (long)blockIdx.z * M) : R;

    int m0 = blockIdx.y * 128, n0 = blockIdx.x * 128;

    float acc[4][4][4];
    #pragma unroll
    for (int i = 0; i < 4; i++)
        #pragma unroll
        for (int j = 0; j < 4; j++)
            #pragma unroll
            for (int e = 0; e < 4; e++) acc[i][j][e] = 0.f;

    gemm_mainloop(A, Bt, M, N, K, m0, n0, fc, acc);

    // ---- EPI 3: stage 16 qss partials per row into smem scratch ----
    float* qs = (float*)smem;
    if (EPI == 3) {
        __syncthreads();
        #pragma unroll
        for (int i = 0; i < 8; i++) {
            int idx = fc.tid + 256 * i;         // 0..2047
            int p = idx >> 7, row = idx & 127;
            qs[row * 17 + p] = Rp[(long)p * ROWS + m0 + row];
        }
        __syncthreads();
    }

    #pragma unroll
    for (int mi = 0; mi < 4; mi++) {
        #pragma unroll
        for (int half_ = 0; half_ < 2; half_++) {
            int m = m0 + fc.wm * 64 + mi * 16 + fc.lr + half_ * 8;
            if (m >= M) continue;
            float rscale = 0.f;
            if (EPI == 3) {
                float ss = 0.f;
                #pragma unroll
                for (int i = 0; i < 16; i++) ss += qs[(m - m0) * 17 + i];
                rscale = 1.f / fmaxf(sqrtf(ss), 1e-6f);
            }
            #pragma unroll
            for (int ni = 0; ni < 4; ni++) {
                int n = n0 + fc.wn * 32 + ni * 8 + 2 * fc.lc;
                if (EPI == 1) {
                    float x0 = acc[mi][ni][half_ * 2 + 0] + bias[n];
                    float x1 = acc[mi][ni][half_ * 2 + 1] + bias[n + 1];
                    x0 = 0.5f * x0 * (1.f + erff(x0 * 0.70710678118654752f));
                    x1 = 0.5f * x1 * (1.f + erff(x1 * 0.70710678118654752f));
                    *(__half2*)(Ch + (long)m * ldc + n) = __floats2half2_rn(x0, x1);
                } else {
                    #pragma unroll
                    for (int e = 0; e < 2; e++) {
                        int ne = n + e;
                        if (ne >= n_store) continue;
                        float x = acc[mi][ni][half_ * 2 + e];
                        if (EPI == 2) x += bias[ne] + Rp[(long)m * ldc + ne];
                        if (EPI == 3) x *= rscale;
                        Cf[(long)m * ldc + ne] = x;
                    }
                }
            }
        }
    }
}

// ---------------------------------------------------------------------------
// top-5 + softmax + gather + gate + residual + fused LN2 (one warp per pixel)
// ---------------------------------------------------------------------------
__global__ void topk_ln2_kernel(const float* __restrict__ logit_scale,
                                const float* __restrict__ alpha_p,
                                const float* __restrict__ g2,
                                const float* __restrict__ b2) {
    int warp = (blockIdx.x * blockDim.x + threadIdx.x) >> 5;
    int lane = threadIdx.x & 31;
    int b = warp >> 12;

    float ls = logit_scale[0];
    float scale = expf(fminf(fmaxf(ls, -2.f), 2.f)) * rsqrtf((float)CT);
    float alpha = alpha_p[0];

    const float* srow = g_sim + (long)warp * TT;
    float vals[4]; int idxs[4];
    #pragma unroll
    for (int i = 0; i < 4; i++) {
        int t = lane + 32 * i;
        if (t < TT) { vals[i] = srow[t] * scale; idxs[i] = t; }
        else        { vals[i] = -INFINITY;       idxs[i] = 0x7fffffff; }
    }

    float wv[TOPM]; int wi[TOPM];
    #pragma unroll
    for (int m = 0; m < TOPM; m++) {
        float bv = vals[0]; int bi = idxs[0];
        #pragma unroll
        for (int i = 1; i < 4; i++)
            if (vals[i] > bv || (vals[i] == bv && idxs[i] < bi)) { bv = vals[i]; bi = idxs[i]; }
        float rv = bv; int ri = bi;
        #pragma unroll
        for (int off = 16; off; off >>= 1) {
            float ov = __shfl_xor_sync(0xffffffffu, rv, off);
            int   oi = __shfl_xor_sync(0xffffffffu, ri, off);
            if (ov > rv || (ov == rv && oi < ri)) { rv = ov; ri = oi; }
        }
        wv[m] = rv; wi[m] = ri;
        if ((ri & 31) == lane) {
            int s = ri >> 5;
            vals[s] = -INFINITY; idxs[s] = 0x7fffffff;
        }
    }

    float mx = -INFINITY;
    #pragma unroll
    for (int m = 0; m < TOPM; m++) {
        if (g_pad[b * TT + wi[m]]) wv[m] = -INFINITY;
        mx = fmaxf(mx, wv[m]);
    }
    float e[TOPM]; float se = 0.f;
    #pragma unroll
    for (int m = 0; m < TOPM; m++) {
        e[m] = (wv[m] == -INFINITY) ? 0.f : expf(wv[m] - mx);
        se += e[m];
    }
    float inv = 1.f / se;
    float ag = alpha * g_gate[warp];

    long rowoff = (long)warp * CV;
    float yv[8];
    #pragma unroll
    for (int j = 0; j < 8; j++) {
        int c = lane + 32 * j;
        float acc = 0.f;
        #pragma unroll
        for (int m = 0; m < TOPM; m++)
            acc = fmaf(e[m] * inv, g_v[(long)(b * TT + wi[m]) * CV + c], acc);
        yv[j] = g_x[rowoff + c] + ag * acc;
    }
    // fused LayerNorm2
    float s = 0.f;
    #pragma unroll
    for (int j = 0; j < 8; j++) s += yv[j];
    float mean = wred(s) * (1.f / CV);
    float sq = 0.f;
    #pragma unroll
    for (int j = 0; j < 8; j++) { float d = yv[j] - mean; sq += d * d; }
    float rs = rsqrtf(wred(sq) * (1.f / CV) + 1e-5f);
    #pragma unroll
    for (int j = 0; j < 8; j++) {
        int c = lane + 32 * j;
        float y2 = (yv[j] - mean) * rs * g2[c] + b2[c];
        g_y2 [rowoff + c] = y2;
        g_y2t[rowoff + c] = __float2half_rn(y2);
    }
}

// ---------------------------------------------------------------------------
// Launch
// ---------------------------------------------------------------------------
static void* symaddr(const void* sym) {
    void* p = nullptr;
    cudaGetSymbolAddress(&p, sym);
    return p;
}

extern "C" void kernel_launch(void* const* d_in, const int* in_sizes, int n_in,
                              void* d_out, int out_size) {
    const float* visual = (const float*)d_in[0];
    const float* text   = (const float*)d_in[1];
    const float* ln1_g  = (const float*)d_in[2];
    const float* ln1_b  = (const float*)d_in[3];
    const float* qw     = (const float*)d_in[4];
    const float* qb     = (const float*)d_in[5];
    const float* vw     = (const float*)d_in[6];
    const float* vb     = (const float*)d_in[7];
    const float* gate_w = (const float*)d_in[8];
    const float* gate_b = (const float*)d_in[9];
    const float* lscale = (const float*)d_in[10];
    const float* alpha  = (const float*)d_in[11];
    const float* ln2_g  = (const float*)d_in[12];
    const float* ln2_b  = (const float*)d_in[13];
    const float* w1     = (const float*)d_in[14];
    const float* b1     = (const float*)d_in[15];
    const float* w2     = (const float*)d_in[16];
    const float* b2     = (const float*)d_in[17];
    float* out = (float*)d_out;

    __half* pq   = (__half*)symaddr(g_q);
    float*  pqss = (float*) symaddr(g_qss);
    __half* pkn  = (__half*)symaddr(g_kn);
    float*  ps   = (float*) symaddr(g_sim);
    float*  py2  = (float*) symaddr(g_y2);
    __half* py2t = (__half*)symaddr(g_y2t);
    __half* ph   = (__half*)symaddr(g_h);
    __half* pw1t = (__half*)symaddr(g_w1t);
    __half* pw2t = (__half*)symaddr(g_w2t);

    cudaFuncSetAttribute(qv_gemm,     cudaFuncAttributeMaxDynamicSharedMemorySize, SMEM_BYTES);
    cudaFuncSetAttribute(mma_gemm<1>, cudaFuncAttributeMaxDynamicSharedMemorySize, SMEM_BYTES);
    cudaFuncSetAttribute(mma_gemm<2>, cudaFuncAttributeMaxDynamicSharedMemorySize, SMEM_BYTES);
    cudaFuncSetAttribute(mma_gemm<3>, cudaFuncAttributeMaxDynamicSharedMemorySize, SMEM_BYTES);

    // 1. prep: weight transposes + LN1/gate + text prep (one launch)
    prep_kernel<<<TR_BLOCKS + LN1_BLOCKS + TEXT_BLOCKS, 256>>>(
        visual, text, qw, vw, w1, w2, ln1_g, ln1_b, gate_w, gate_b);

    // 2. Q (+qss) and V GEMMs fused in one launch
    qv_gemm<<<1024 + 14, 256, SMEM_BYTES>>>(qb, vb);

    // 3. sim = (q @ k^T) * rsqrt(sum qss)  (4096 x 100(->128) x 512, batched)
    mma_gemm<3><<<dim3(1, NN_/128, BB), 256, SMEM_BYTES>>>(
        pq, pkn, nullptr, pqss, ps, NN_, TPAD, CT, TT, TT,
        (long)NN_*CT, (long)TPAD*CT, (long)NN_*TT);

    // 4. top-5 + softmax + gather + gate + residual + LN2
    topk_ln2_kernel<<<ROWS/8, 256>>>(lscale, alpha, ln2_g, ln2_b);

    // 5. h = gelu(y2 @ w1 + b1) -> fp16   (32768 x 1024 x 256)
    mma_gemm<1><<<dim3(4*CV/128, ROWS/128, 1), 256, SMEM_BYTES>>>(
        py2t, pw1t, b1, nullptr, ph, ROWS, 4*CV, CV, 4*CV, 4*CV, 0, 0, 0);

    // 6. out = y2 + h @ w2 + b2 -> fp32   (32768 x 256 x 1024)
    mma_gemm<2><<<dim3(CV/128, ROWS/128, 1), 256, SMEM_BYTES>>>(
        ph, pw2t, b2, py2, out, ROWS, CV, 4*CV, CV, CV, 0, 0, 0);
}